// round 12
// baseline (speedup 1.0000x reference)
#include <cuda_runtime.h>
#include <cuda_fp16.h>
#include <cstdint>
#include <math.h>

#define B_   2
#define S_   2048
#define HID_ 1024
#define NH_  16
#define HD_  64
#define MTOT (B_ * S_)   // 4096
#define QSCALE 0.1803368801111204f      // 0.125 * log2(e)

// ---------------------------------------------------------------------------
// Scratch buffers (no cudaMalloc allowed). All fp16.
// g_v holds V TRANSPOSED per (b,h): layout [(b*16+h)*64 + d][s], pitch S_.
// ---------------------------------------------------------------------------
__device__ __half g_q[MTOT * HID_];
__device__ __half g_k[MTOT * HID_];
__device__ __half g_v[MTOT * HID_];
__device__ __half g_attn[MTOT * HID_];
__device__ __half g_xt[MTOT * HID_];
__device__ __half g_wt[3 * HID_ * HID_];
__device__ __half g_wo[HID_ * HID_];

// ---------------------------------------------------------------------------
// Helpers
// ---------------------------------------------------------------------------
__device__ __forceinline__ uint32_t smem_u32(const void* p) {
    uint32_t a;
    asm("{ .reg .u64 t; cvta.to.shared.u64 t, %1; cvt.u32.u64 %0, t; }"
        : "=r"(a) : "l"(p));
    return a;
}

__device__ __forceinline__ void ldmatrix_x4(uint32_t& r0, uint32_t& r1,
                                            uint32_t& r2, uint32_t& r3,
                                            uint32_t addr) {
    asm volatile("ldmatrix.sync.aligned.m8n8.x4.shared.b16 {%0,%1,%2,%3}, [%4];"
                 : "=r"(r0), "=r"(r1), "=r"(r2), "=r"(r3) : "r"(addr));
}

__device__ __forceinline__ void mma_f16(float& c0, float& c1, float& c2, float& c3,
                                        uint32_t a0, uint32_t a1, uint32_t a2,
                                        uint32_t a3, uint32_t b0, uint32_t b1) {
    asm volatile(
        "mma.sync.aligned.m16n8k16.row.col.f32.f16.f16.f32 "
        "{%0,%1,%2,%3}, {%4,%5,%6,%7}, {%8,%9}, {%0,%1,%2,%3};"
        : "+f"(c0), "+f"(c1), "+f"(c2), "+f"(c3)
        : "r"(a0), "r"(a1), "r"(a2), "r"(a3), "r"(b0), "r"(b1));
}

__device__ __forceinline__ float quad_max(float v) {
    v = fmaxf(v, __shfl_xor_sync(0xffffffffu, v, 1));
    v = fmaxf(v, __shfl_xor_sync(0xffffffffu, v, 2));
    return v;
}
__device__ __forceinline__ float quad_sum(float v) {
    v += __shfl_xor_sync(0xffffffffu, v, 1);
    v += __shfl_xor_sync(0xffffffffu, v, 2);
    return v;
}

#define CPA16(dst, src) \
    asm volatile("cp.async.cg.shared.global [%0], [%1], 16;" \
                 :: "r"(dst), "l"(src) : "memory")
#define CPA_COMMIT() asm volatile("cp.async.commit_group;" ::: "memory")
#define CPA_WAIT1()  asm volatile("cp.async.wait_group 1;" ::: "memory")
#define CPA_WAIT0()  asm volatile("cp.async.wait_group 0;" ::: "memory")

// ---------------------------------------------------------------------------
// fp32 -> fp16 conversion passes
// ---------------------------------------------------------------------------
__global__ void __launch_bounds__(256)
to_half(const float* __restrict__ in, __half* __restrict__ out, int n4)
{
    int i = blockIdx.x * 256 + threadIdx.x;
    if (i < n4) {
        float4 v = ((const float4*)in)[i];
        __half2* o = (__half2*)(out + 4 * (size_t)i);
        o[0] = __floats2half2_rn(v.x, v.y);
        o[1] = __floats2half2_rn(v.z, v.w);
    }
}

__global__ void __launch_bounds__(256)
to_half_w4(const float* __restrict__ w0, const float* __restrict__ w1,
           const float* __restrict__ w2, const float* __restrict__ w3,
           __half* __restrict__ o0, __half* __restrict__ o1,
           __half* __restrict__ o2, __half* __restrict__ o3, int n4)
{
    const float* in; __half* out;
    if (blockIdx.z == 0)      { in = w0; out = o0; }
    else if (blockIdx.z == 1) { in = w1; out = o1; }
    else if (blockIdx.z == 2) { in = w2; out = o2; }
    else                      { in = w3; out = o3; }
    int i = blockIdx.x * 256 + threadIdx.x;
    if (i < n4) {
        float4 v = ((const float4*)in)[i];
        __half2* o = (__half2*)(out + 4 * (size_t)i);
        o[0] = __floats2half2_rn(v.x, v.y);
        o[1] = __floats2half2_rn(v.z, v.w);
    }
}

// ---------------------------------------------------------------------------
// fp16 mma.sync GEMM (m16n8k16), cp.async 3-stage pipeline, 256 threads
// (8 warps 2x4), CTA tile 128x128x64, warp tile 64x32, 2 CTAs/SM.
//   C[M,N] = A[M,K] @ W[N,K]^T + bias[N]      (A, W fp16, fp32 accum)
// mode: 0 fp32 store; 1 fp16 store; 2 fp16 store transposed per (b,h);
//       3 fp16 store scaled by QSCALE (for Q).
// ---------------------------------------------------------------------------
#define STAGE_BYTES 32768
#define GEMM_SMEM (3 * STAGE_BYTES)        // 98304

__global__ void __launch_bounds__(256, 2)
gemm_tc(const __half* __restrict__ A,
        const __half* __restrict__ W0, const __half* __restrict__ W1,
        const __half* __restrict__ W2,
        const float* __restrict__ b0_, const float* __restrict__ b1_,
        const float* __restrict__ b2_,
        void* __restrict__ C0, void* __restrict__ C1, void* __restrict__ C2,
        int M, int N, int K, int mode0, int mode1, int mode2)
{
    extern __shared__ char smc[];
    const uint32_t sbase = smem_u32(smc);
    const int tid  = threadIdx.x;
    const int wid  = tid >> 5;
    const int lane = tid & 31;
    const int warpM = wid & 1;          // 2 warp-rows (64 rows each)
    const int warpN = wid >> 1;         // 4 warp-cols (32 cols each)

    const __half* W; const float* bias; void* C; int mode;
    if (blockIdx.z == 0)      { W = W0; bias = b0_; C = C0; mode = mode0; }
    else if (blockIdx.z == 1) { W = W1; bias = b1_; C = C1; mode = mode1; }
    else                      { W = W2; bias = b2_; C = C2; mode = mode2; }

    const int rowM = blockIdx.y * 128;
    const int colN = blockIdx.x * 128;
    const __half* Ag = A + (size_t)rowM * K;
    const __half* Wg = W + (size_t)colN * K;

    // cp.async: 256 threads; thread -> (row, 4 x 16B units) for A and W
    const int cr = tid >> 1;            // 0..127
    const int cu = (tid & 1) * 4;       // 0 or 4
    const __half* agr = Ag + (size_t)cr * K;
    const __half* wgr = Wg + (size_t)cr * K;

    const int a_row = lane & 15;
    const int a_u   = lane >> 4;
    const int b_row = ((lane >> 4) & 1) * 8 + (lane & 7);
    const int b_u   = (lane >> 3) & 1;

    float acc[4][4][4];
    #pragma unroll
    for (int mt = 0; mt < 4; mt++)
        #pragma unroll
        for (int nt = 0; nt < 4; nt++)
            #pragma unroll
            for (int q = 0; q < 4; q++) acc[mt][nt][q] = 0.0f;

    const int NC = K / 64;               // 16 chunks

    #pragma unroll
    for (int s = 0; s < 2; s++) {
        const uint32_t sa = sbase + s * STAGE_BYTES + cr * 128;
        const __half* ac = agr + s * 64;
        const __half* wc = wgr + s * 64;
        #pragma unroll
        for (int i = 0; i < 4; i++) {
            const int u = cu + i;
            const uint32_t off = (uint32_t)((u ^ (cr & 7)) << 4);
            CPA16(sa + off,         ac + u * 8);
            CPA16(sa + 16384 + off, wc + u * 8);
        }
        CPA_COMMIT();
    }

    for (int c = 0; c < NC; c++) {
        const int buf = c % 3;
        CPA_WAIT1();
        __syncthreads();

        if (c + 2 < NC) {
            const int s = (c + 2) % 3;
            const uint32_t sa = sbase + s * STAGE_BYTES + cr * 128;
            const __half* ac = agr + (c + 2) * 64;
            const __half* wc = wgr + (c + 2) * 64;
            #pragma unroll
            for (int i = 0; i < 4; i++) {
                const int u = cu + i;
                const uint32_t off = (uint32_t)((u ^ (cr & 7)) << 4);
                CPA16(sa + off,         ac + u * 8);
                CPA16(sa + 16384 + off, wc + u * 8);
            }
        }
        CPA_COMMIT();

        const uint32_t stA = sbase + buf * STAGE_BYTES;
        const uint32_t stB = stA + 16384;
        #pragma unroll
        for (int kc = 0; kc < 4; kc++) {
            uint32_t af[4][4];
            #pragma unroll
            for (int mt = 0; mt < 4; mt++) {
                const int row = warpM * 64 + mt * 16 + a_row;
                const uint32_t addr = stA + (uint32_t)(row * 128) +
                    (uint32_t)((((kc * 2 + a_u) ^ (row & 7))) << 4);
                ldmatrix_x4(af[mt][0], af[mt][1], af[mt][2], af[mt][3], addr);
            }
            uint32_t bf[4][2];
            #pragma unroll
            for (int nb = 0; nb < 2; nb++) {
                const int row = warpN * 32 + nb * 16 + b_row;
                const uint32_t addr = stB + (uint32_t)(row * 128) +
                    (uint32_t)((((kc * 2 + b_u) ^ (row & 7))) << 4);
                uint32_t r0, r1, r2, r3;
                ldmatrix_x4(r0, r1, r2, r3, addr);
                bf[nb * 2 + 0][0] = r0; bf[nb * 2 + 0][1] = r1;
                bf[nb * 2 + 1][0] = r2; bf[nb * 2 + 1][1] = r3;
            }
            #pragma unroll
            for (int mt = 0; mt < 4; mt++)
                #pragma unroll
                for (int nt = 0; nt < 4; nt++)
                    mma_f16(acc[mt][nt][0], acc[mt][nt][1],
                            acc[mt][nt][2], acc[mt][nt][3],
                            af[mt][0], af[mt][1], af[mt][2], af[mt][3],
                            bf[nt][0], bf[nt][1]);
        }
    }

    const int g = lane >> 2;
    const int t = lane & 3;
    float bb[4][2];
    #pragma unroll
    for (int nt = 0; nt < 4; nt++) {
        const int col = colN + warpN * 32 + nt * 8 + 2 * t;
        bb[nt][0] = __ldg(bias + col);
        bb[nt][1] = __ldg(bias + col + 1);
    }
    if (mode == 0) {
        float* Cf = (float*)C;
        #pragma unroll
        for (int mt = 0; mt < 4; mt++) {
            const int r0_ = rowM + warpM * 64 + mt * 16 + g;
            #pragma unroll
            for (int nt = 0; nt < 4; nt++) {
                const int col = colN + warpN * 32 + nt * 8 + 2 * t;
                float2 v0, v1;
                v0.x = acc[mt][nt][0] + bb[nt][0];
                v0.y = acc[mt][nt][1] + bb[nt][1];
                v1.x = acc[mt][nt][2] + bb[nt][0];
                v1.y = acc[mt][nt][3] + bb[nt][1];
                *(float2*)(Cf + (size_t)r0_ * N + col)       = v0;
                *(float2*)(Cf + (size_t)(r0_ + 8) * N + col) = v1;
            }
        }
    } else if (mode == 2) {
        __half* Ch = (__half*)C;
        #pragma unroll
        for (int mt = 0; mt < 4; mt++) {
            const int r0_ = rowM + warpM * 64 + mt * 16 + g;
            const int b0i = r0_ >> 11, s0 = r0_ & 2047;
            const int b1i = (r0_ + 8) >> 11, s1 = (r0_ + 8) & 2047;
            #pragma unroll
            for (int nt = 0; nt < 4; nt++) {
                const int col = colN + warpN * 32 + nt * 8 + 2 * t;
                Ch[((size_t)(b0i * 1024 + col))     * 2048 + s0] = __float2half_rn(acc[mt][nt][0] + bb[nt][0]);
                Ch[((size_t)(b0i * 1024 + col + 1)) * 2048 + s0] = __float2half_rn(acc[mt][nt][1] + bb[nt][1]);
                Ch[((size_t)(b1i * 1024 + col))     * 2048 + s1] = __float2half_rn(acc[mt][nt][2] + bb[nt][0]);
                Ch[((size_t)(b1i * 1024 + col + 1)) * 2048 + s1] = __float2half_rn(acc[mt][nt][3] + bb[nt][1]);
            }
        }
    } else {
        __half* Ch = (__half*)C;
        const float sc = (mode == 3) ? QSCALE : 1.0f;
        #pragma unroll
        for (int mt = 0; mt < 4; mt++) {
            const int r0_ = rowM + warpM * 64 + mt * 16 + g;
            #pragma unroll
            for (int nt = 0; nt < 4; nt++) {
                const int col = colN + warpN * 32 + nt * 8 + 2 * t;
                *(__half2*)(Ch + (size_t)r0_ * N + col) =
                    __floats2half2_rn((acc[mt][nt][0] + bb[nt][0]) * sc,
                                      (acc[mt][nt][1] + bb[nt][1]) * sc);
                *(__half2*)(Ch + (size_t)(r0_ + 8) * N + col) =
                    __floats2half2_rn((acc[mt][nt][2] + bb[nt][0]) * sc,
                                      (acc[mt][nt][3] + bb[nt][1]) * sc);
            }
        }
    }
}

// ---------------------------------------------------------------------------
// fp16 flash attention, FA-2 register P.  (unchanged from round 11 — 139us)
// ---------------------------------------------------------------------------
#define BQ 128
#define BK 64
#define PITCHB 144                         // 72 halfs per row
#define KVBUF_B (2 * BK * PITCHB)          // 18432 B
#define ATTN_SMEM (2 * KVBUF_B)            // 36864 B

__global__ void __launch_bounds__(256, 2)
attn_tc(const __half* __restrict__ Q, const __half* __restrict__ Kg_,
        const __half* __restrict__ Vt_, __half* __restrict__ O)
{
    extern __shared__ char smc[];

    const int tid  = threadIdx.x;
    const int wid  = tid >> 5;
    const int lane = tid & 31;
    const int g    = lane >> 2;
    const int t    = lane & 3;
    const int bh   = blockIdx.y;
    const int b    = bh / NH_;
    const int h    = bh % NH_;
    const int q0   = blockIdx.x * BQ;

    const uint32_t uB0 = smem_u32(smc);
    const uint32_t uB1 = uB0 + KVBUF_B;

    const int a_row = lane & 15;
    const int a_u   = lane >> 4;
    const int b_row = ((lane >> 4) & 1) * 8 + (lane & 7);
    const int b_u   = (lane >> 3) & 1;

    const __half* Kg  = Kg_ + (size_t)(b * S_) * HID_ + h * HD_;
    const __half* Vtg = Vt_ + (size_t)(b * 1024 + h * 64) * 2048;

    const int lr = tid >> 2;            // 0..63
    const int lu = (tid & 3) * 2;       // 0,2,4,6

    {
        const uint32_t dk = uB0 + (uint32_t)(lr * PITCHB + lu * 16);
        const uint32_t dv = dk + (uint32_t)(BK * PITCHB);
        const __half* ks = Kg  + (size_t)lr * HID_ + lu * 8;
        const __half* vs = Vtg + (size_t)lr * 2048 + lu * 8;
        #pragma unroll
        for (int i = 0; i < 2; i++) {
            CPA16(dk + i * 16, ks + i * 8);
            CPA16(dv + i * 16, vs + i * 8);
        }
        CPA_COMMIT();
    }

    {
        const int qr = tid >> 1;
        const int qu = (tid & 1) * 4;
        const uint32_t dq = uB1 + (uint32_t)(qr * PITCHB + qu * 16);
        const __half* qs = Q + (size_t)(b * S_ + q0 + qr) * HID_ + h * HD_ + qu * 8;
        #pragma unroll
        for (int i = 0; i < 4; i++) CPA16(dq + i * 16, qs + i * 8);
        CPA_COMMIT();
    }
    CPA_WAIT0();
    __syncthreads();

    uint32_t qf[4][4];
    #pragma unroll
    for (int kc = 0; kc < 4; kc++)
        ldmatrix_x4(qf[kc][0], qf[kc][1], qf[kc][2], qf[kc][3],
            uB1 + (uint32_t)((wid * 16 + a_row) * PITCHB + (kc * 2 + a_u) * 16));
    __syncthreads();

    float o[8][4];
    #pragma unroll
    for (int nt = 0; nt < 8; nt++)
        #pragma unroll
        for (int q = 0; q < 4; q++) o[nt][q] = 0.0f;
    float m0 = -1e30f, m1 = -1e30f, l0 = 0.0f, l1 = 0.0f;

    const int NT = S_ / BK;   // 32

    for (int kt = 0; kt < NT; kt++) {
        const uint32_t uKb  = (kt & 1) ? uB1 : uB0;
        const uint32_t uVtb = uKb + (uint32_t)(BK * PITCHB);

        if (kt + 1 < NT) {
            const uint32_t dst = (kt & 1) ? uB0 : uB1;
            const uint32_t dk = dst + (uint32_t)(lr * PITCHB + lu * 16);
            const uint32_t dv = dk + (uint32_t)(BK * PITCHB);
            const __half* ks = Kg  + (size_t)((kt + 1) * BK + lr) * HID_ + lu * 8;
            const __half* vs = Vtg + (size_t)lr * 2048 + (kt + 1) * BK + lu * 8;
            #pragma unroll
            for (int i = 0; i < 2; i++) {
                CPA16(dk + i * 16, ks + i * 8);
                CPA16(dv + i * 16, vs + i * 8);
            }
            CPA_COMMIT();
            CPA_WAIT1();
        } else {
            CPA_WAIT0();
        }
        __syncthreads();

        float s[8][4];
        #pragma unroll
        for (int nt = 0; nt < 8; nt++)
            #pragma unroll
            for (int q = 0; q < 4; q++) s[nt][q] = 0.0f;

        #pragma unroll
        for (int kc = 0; kc < 4; kc++) {
            uint32_t bf[8][2];
            #pragma unroll
            for (int nb = 0; nb < 4; nb++) {
                uint32_t r0, r1, r2, r3;
                ldmatrix_x4(r0, r1, r2, r3,
                    uKb + (uint32_t)((nb * 16 + b_row) * PITCHB + (kc * 2 + b_u) * 16));
                bf[nb * 2 + 0][0] = r0; bf[nb * 2 + 0][1] = r1;
                bf[nb * 2 + 1][0] = r2; bf[nb * 2 + 1][1] = r3;
            }
            #pragma unroll
            for (int nt = 0; nt < 8; nt++)
                mma_f16(s[nt][0], s[nt][1], s[nt][2], s[nt][3],
                        qf[kc][0], qf[kc][1], qf[kc][2], qf[kc][3],
                        bf[nt][0], bf[nt][1]);
        }

        float mx0 = -1e30f, mx1 = -1e30f;
        #pragma unroll
        for (int nt = 0; nt < 8; nt++) {
            mx0 = fmaxf(mx0, fmaxf(s[nt][0], s[nt][1]));
            mx1 = fmaxf(mx1, fmaxf(s[nt][2], s[nt][3]));
        }
        mx0 = quad_max(mx0); mx1 = quad_max(mx1);
        const float mn0 = fmaxf(m0, mx0);
        const float mn1 = fmaxf(m1, mx1);
        const float c0r = exp2f(m0 - mn0);
        const float c1r = exp2f(m1 - mn1);
        m0 = mn0; m1 = mn1;

        uint32_t ph[8][2];
        float sum0 = 0.0f, sum1 = 0.0f;
        #pragma unroll
        for (int nt = 0; nt < 8; nt++) {
            float p0 = exp2f(s[nt][0] - mn0);
            float p1 = exp2f(s[nt][1] - mn0);
            float p2 = exp2f(s[nt][2] - mn1);
            float p3 = exp2f(s[nt][3] - mn1);
            sum0 += p0 + p1;
            sum1 += p2 + p3;
            o[nt][0] *= c0r; o[nt][1] *= c0r;
            o[nt][2] *= c1r; o[nt][3] *= c1r;
            __half2 h01 = __floats2half2_rn(p0, p1);
            __half2 h23 = __floats2half2_rn(p2, p3);
            ph[nt][0] = *(uint32_t*)&h01;
            ph[nt][1] = *(uint32_t*)&h23;
        }
        sum0 = quad_sum(sum0); sum1 = quad_sum(sum1);
        l0 = l0 * c0r + sum0;
        l1 = l1 * c1r + sum1;

        #pragma unroll
        for (int kc = 0; kc < 4; kc++) {
            uint32_t vf[8][2];
            #pragma unroll
            for (int nb = 0; nb < 4; nb++) {
                uint32_t r0, r1, r2, r3;
                ldmatrix_x4(r0, r1, r2, r3,
                    uVtb + (uint32_t)((nb * 16 + b_row) * PITCHB + (kc * 2 + b_u) * 16));
                vf[nb * 2 + 0][0] = r0; vf[nb * 2 + 0][1] = r1;
                vf[nb * 2 + 1][0] = r2; vf[nb * 2 + 1][1] = r3;
            }
            #pragma unroll
            for (int nt = 0; nt < 8; nt++)
                mma_f16(o[nt][0], o[nt][1], o[nt][2], o[nt][3],
                        ph[2 * kc][0], ph[2 * kc][1],
                        ph[2 * kc + 1][0], ph[2 * kc + 1][1],
                        vf[nt][0], vf[nt][1]);
        }
        __syncthreads();
    }

    const float inv0 = 1.0f / l0;
    const float inv1 = 1.0f / l1;
    __half* Or = O + (size_t)(b * S_ + q0 + wid * 16 + g) * HID_ + h * HD_;
    #pragma unroll
    for (int nt = 0; nt < 8; nt++) {
        *(__half2*)(Or + nt * 8 + 2 * t) =
            __floats2half2_rn(o[nt][0] * inv0, o[nt][1] * inv0);
        *(__half2*)(Or + 8 * HID_ + nt * 8 + 2 * t) =
            __floats2half2_rn(o[nt][2] * inv1, o[nt][3] * inv1);
    }
}

// ---------------------------------------------------------------------------
// Launch
// ---------------------------------------------------------------------------
extern "C" void kernel_launch(void* const* d_in, const int* in_sizes, int n_in,
                              void* d_out, int out_size)
{
    const float* x  = (const float*)d_in[0];
    const float* Wq = (const float*)d_in[1];
    const float* bq = (const float*)d_in[2];
    const float* Wk = (const float*)d_in[3];
    const float* bk = (const float*)d_in[4];
    const float* Wv = (const float*)d_in[5];
    const float* bv = (const float*)d_in[6];
    const float* Wo = (const float*)d_in[7];
    const float* bo = (const float*)d_in[8];
    float* out = (float*)d_out;

    __half *qp, *kp, *vp, *ap, *xt, *wt, *wo;
    cudaGetSymbolAddress((void**)&qp, g_q);
    cudaGetSymbolAddress((void**)&kp, g_k);
    cudaGetSymbolAddress((void**)&vp, g_v);
    cudaGetSymbolAddress((void**)&ap, g_attn);
    cudaGetSymbolAddress((void**)&xt, g_xt);
    cudaGetSymbolAddress((void**)&wt, g_wt);
    cudaGetSymbolAddress((void**)&wo, g_wo);

    cudaFuncSetAttribute(gemm_tc, cudaFuncAttributeMaxDynamicSharedMemorySize,
                         GEMM_SMEM);
    cudaFuncSetAttribute(attn_tc, cudaFuncAttributeMaxDynamicSharedMemorySize,
                         ATTN_SMEM);

    // 0) convert inputs/weights to fp16
    {
        const int NX4 = MTOT * HID_ / 4;
        const int NW4 = HID_ * HID_ / 4;
        to_half<<<NX4 / 256, 256>>>(x, xt, NX4);
        dim3 wg(NW4 / 256, 1, 4);
        to_half_w4<<<wg, 256>>>(Wq, Wk, Wv, Wo,
                                wt, wt + HID_ * HID_, wt + 2 * HID_ * HID_, wo,
                                NW4);
    }

    // 1) fused QKV projections: q scaled (mode 3), k fp16 (mode 1),
    //    v fp16 transposed per head (mode 2)
    {
        dim3 grid(HID_ / 128, MTOT / 128, 3);
        gemm_tc<<<grid, 256, GEMM_SMEM>>>(xt, wt, wt + HID_ * HID_,
                                          wt + 2 * HID_ * HID_,
                                          bq, bk, bv,
                                          (void*)qp, (void*)kp, (void*)vp,
                                          MTOT, HID_, HID_, 3, 1, 2);
    }

    // 2) attention (fp16 m16n8k16, register-P flash attention)
    {
        dim3 grid(S_ / BQ, B_ * NH_);
        attn_tc<<<grid, 256, ATTN_SMEM>>>(qp, kp, vp, ap);
    }

    // 3) output projection (fp32 out)
    {
        dim3 grid(HID_ / 128, MTOT / 128, 1);
        gemm_tc<<<grid, 256, GEMM_SMEM>>>(ap, wo, wo, wo, bo, bo, bo,
                                          (void*)out, (void*)out, (void*)out,
                                          MTOT, HID_, HID_, 0, 0, 0);
    }
}

// round 13
// speedup vs baseline: 1.0212x; 1.0212x over previous
#include <cuda_runtime.h>
#include <cuda_fp16.h>
#include <cstdint>
#include <math.h>

#define B_   2
#define S_   2048
#define HID_ 1024
#define NH_  16
#define HD_  64
#define MTOT (B_ * S_)   // 4096
#define QSCALE 0.1803368801111204f      // 0.125 * log2(e)

// ---------------------------------------------------------------------------
// Scratch buffers (no cudaMalloc allowed). All fp16, standard layouts.
// ---------------------------------------------------------------------------
__device__ __half g_q[MTOT * HID_];
__device__ __half g_k[MTOT * HID_];
__device__ __half g_v[MTOT * HID_];
__device__ __half g_attn[MTOT * HID_];
__device__ __half g_xt[MTOT * HID_];
__device__ __half g_wt[3 * HID_ * HID_];
__device__ __half g_wo[HID_ * HID_];

// ---------------------------------------------------------------------------
// Helpers
// ---------------------------------------------------------------------------
__device__ __forceinline__ uint32_t smem_u32(const void* p) {
    uint32_t a;
    asm("{ .reg .u64 t; cvta.to.shared.u64 t, %1; cvt.u32.u64 %0, t; }"
        : "=r"(a) : "l"(p));
    return a;
}

__device__ __forceinline__ void ldmatrix_x4(uint32_t& r0, uint32_t& r1,
                                            uint32_t& r2, uint32_t& r3,
                                            uint32_t addr) {
    asm volatile("ldmatrix.sync.aligned.m8n8.x4.shared.b16 {%0,%1,%2,%3}, [%4];"
                 : "=r"(r0), "=r"(r1), "=r"(r2), "=r"(r3) : "r"(addr));
}

__device__ __forceinline__ void ldmatrix_x4_trans(uint32_t& r0, uint32_t& r1,
                                                  uint32_t& r2, uint32_t& r3,
                                                  uint32_t addr) {
    asm volatile("ldmatrix.sync.aligned.m8n8.x4.trans.shared.b16 {%0,%1,%2,%3}, [%4];"
                 : "=r"(r0), "=r"(r1), "=r"(r2), "=r"(r3) : "r"(addr));
}

__device__ __forceinline__ void mma_f16(float& c0, float& c1, float& c2, float& c3,
                                        uint32_t a0, uint32_t a1, uint32_t a2,
                                        uint32_t a3, uint32_t b0, uint32_t b1) {
    asm volatile(
        "mma.sync.aligned.m16n8k16.row.col.f32.f16.f16.f32 "
        "{%0,%1,%2,%3}, {%4,%5,%6,%7}, {%8,%9}, {%0,%1,%2,%3};"
        : "+f"(c0), "+f"(c1), "+f"(c2), "+f"(c3)
        : "r"(a0), "r"(a1), "r"(a2), "r"(a3), "r"(b0), "r"(b1));
}

__device__ __forceinline__ float quad_max(float v) {
    v = fmaxf(v, __shfl_xor_sync(0xffffffffu, v, 1));
    v = fmaxf(v, __shfl_xor_sync(0xffffffffu, v, 2));
    return v;
}
__device__ __forceinline__ float quad_sum(float v) {
    v += __shfl_xor_sync(0xffffffffu, v, 1);
    v += __shfl_xor_sync(0xffffffffu, v, 2);
    return v;
}

#define CPA16(dst, src) \
    asm volatile("cp.async.cg.shared.global [%0], [%1], 16;" \
                 :: "r"(dst), "l"(src) : "memory")
#define CPA_COMMIT() asm volatile("cp.async.commit_group;" ::: "memory")
#define CPA_WAIT2()  asm volatile("cp.async.wait_group 2;" ::: "memory")
#define CPA_WAIT1()  asm volatile("cp.async.wait_group 1;" ::: "memory")
#define CPA_WAIT0()  asm volatile("cp.async.wait_group 0;" ::: "memory")

// ---------------------------------------------------------------------------
// fp32 -> fp16 conversion passes
// ---------------------------------------------------------------------------
__global__ void __launch_bounds__(256)
to_half(const float* __restrict__ in, __half* __restrict__ out, int n4)
{
    int i = blockIdx.x * 256 + threadIdx.x;
    if (i < n4) {
        float4 v = ((const float4*)in)[i];
        __half2* o = (__half2*)(out + 4 * (size_t)i);
        o[0] = __floats2half2_rn(v.x, v.y);
        o[1] = __floats2half2_rn(v.z, v.w);
    }
}

__global__ void __launch_bounds__(256)
to_half_w4(const float* __restrict__ w0, const float* __restrict__ w1,
           const float* __restrict__ w2, const float* __restrict__ w3,
           __half* __restrict__ o0, __half* __restrict__ o1,
           __half* __restrict__ o2, __half* __restrict__ o3, int n4)
{
    const float* in; __half* out;
    if (blockIdx.z == 0)      { in = w0; out = o0; }
    else if (blockIdx.z == 1) { in = w1; out = o1; }
    else if (blockIdx.z == 2) { in = w2; out = o2; }
    else                      { in = w3; out = o3; }
    int i = blockIdx.x * 256 + threadIdx.x;
    if (i < n4) {
        float4 v = ((const float4*)in)[i];
        __half2* o = (__half2*)(out + 4 * (size_t)i);
        o[0] = __floats2half2_rn(v.x, v.y);
        o[1] = __floats2half2_rn(v.z, v.w);
    }
}

// ---------------------------------------------------------------------------
// fp16 mma.sync GEMM (m16n8k16), cp.async 4-stage pipeline, 512 threads
// (16 warps 4x4), CTA tile 128x128x64, warp tile 32x32.  (round-11 proven)
// mode: 0 fp32 store; 1 fp16 store; 3 fp16 store scaled by QSCALE (Q).
// ---------------------------------------------------------------------------
#define STAGE_BYTES 32768
#define GEMM_SMEM (4 * STAGE_BYTES)        // 131072

__global__ void __launch_bounds__(512)
gemm_tc(const __half* __restrict__ A,
        const __half* __restrict__ W0, const __half* __restrict__ W1,
        const __half* __restrict__ W2,
        const float* __restrict__ b0_, const float* __restrict__ b1_,
        const float* __restrict__ b2_,
        void* __restrict__ C0, void* __restrict__ C1, void* __restrict__ C2,
        int M, int N, int K, int mode0, int mode1, int mode2)
{
    extern __shared__ char smc[];
    const uint32_t sbase = smem_u32(smc);
    const int tid  = threadIdx.x;
    const int wid  = tid >> 5;
    const int lane = tid & 31;
    const int warpM = wid & 3;
    const int warpN = wid >> 2;

    const __half* W; const float* bias; void* C; int mode;
    if (blockIdx.z == 0)      { W = W0; bias = b0_; C = C0; mode = mode0; }
    else if (blockIdx.z == 1) { W = W1; bias = b1_; C = C1; mode = mode1; }
    else                      { W = W2; bias = b2_; C = C2; mode = mode2; }

    const int rowM = blockIdx.y * 128;
    const int colN = blockIdx.x * 128;
    const __half* Ag = A + (size_t)rowM * K;
    const __half* Wg = W + (size_t)colN * K;

    const int cr = tid >> 2;            // 0..127
    const int cu = (tid & 3) * 2;       // 0,2,4,6
    const __half* agr = Ag + (size_t)cr * K;
    const __half* wgr = Wg + (size_t)cr * K;

    const int a_row = lane & 15;
    const int a_u   = lane >> 4;
    const int b_row = ((lane >> 4) & 1) * 8 + (lane & 7);
    const int b_u   = (lane >> 3) & 1;

    float acc[2][4][4];
    #pragma unroll
    for (int mt = 0; mt < 2; mt++)
        #pragma unroll
        for (int nt = 0; nt < 4; nt++)
            #pragma unroll
            for (int q = 0; q < 4; q++) acc[mt][nt][q] = 0.0f;

    const int NC = K / 64;               // 16 chunks

    #pragma unroll
    for (int s = 0; s < 3; s++) {
        const uint32_t sa = sbase + s * STAGE_BYTES + cr * 128;
        const __half* ac = agr + s * 64;
        const __half* wc = wgr + s * 64;
        #pragma unroll
        for (int i = 0; i < 2; i++) {
            const int u = cu + i;
            const uint32_t off = (uint32_t)((u ^ (cr & 7)) << 4);
            CPA16(sa + off,         ac + u * 8);
            CPA16(sa + 16384 + off, wc + u * 8);
        }
        CPA_COMMIT();
    }

    for (int c = 0; c < NC; c++) {
        const int buf = c & 3;
        CPA_WAIT2();
        __syncthreads();

        if (c + 3 < NC) {
            const int s = (c + 3) & 3;
            const uint32_t sa = sbase + s * STAGE_BYTES + cr * 128;
            const __half* ac = agr + (c + 3) * 64;
            const __half* wc = wgr + (c + 3) * 64;
            #pragma unroll
            for (int i = 0; i < 2; i++) {
                const int u = cu + i;
                const uint32_t off = (uint32_t)((u ^ (cr & 7)) << 4);
                CPA16(sa + off,         ac + u * 8);
                CPA16(sa + 16384 + off, wc + u * 8);
            }
        }
        CPA_COMMIT();

        const uint32_t stA = sbase + buf * STAGE_BYTES;
        const uint32_t stB = stA + 16384;
        #pragma unroll
        for (int kc = 0; kc < 4; kc++) {
            uint32_t af[2][4];
            #pragma unroll
            for (int mt = 0; mt < 2; mt++) {
                const int row = warpM * 32 + mt * 16 + a_row;
                const uint32_t addr = stA + (uint32_t)(row * 128) +
                    (uint32_t)((((kc * 2 + a_u) ^ (row & 7))) << 4);
                ldmatrix_x4(af[mt][0], af[mt][1], af[mt][2], af[mt][3], addr);
            }
            uint32_t bf[4][2];
            #pragma unroll
            for (int nb = 0; nb < 2; nb++) {
                const int row = warpN * 32 + nb * 16 + b_row;
                const uint32_t addr = stB + (uint32_t)(row * 128) +
                    (uint32_t)((((kc * 2 + b_u) ^ (row & 7))) << 4);
                uint32_t r0, r1, r2, r3;
                ldmatrix_x4(r0, r1, r2, r3, addr);
                bf[nb * 2 + 0][0] = r0; bf[nb * 2 + 0][1] = r1;
                bf[nb * 2 + 1][0] = r2; bf[nb * 2 + 1][1] = r3;
            }
            #pragma unroll
            for (int mt = 0; mt < 2; mt++)
                #pragma unroll
                for (int nt = 0; nt < 4; nt++)
                    mma_f16(acc[mt][nt][0], acc[mt][nt][1],
                            acc[mt][nt][2], acc[mt][nt][3],
                            af[mt][0], af[mt][1], af[mt][2], af[mt][3],
                            bf[nt][0], bf[nt][1]);
        }
    }

    const int g = lane >> 2;
    const int t = lane & 3;
    float bb[4][2];
    #pragma unroll
    for (int nt = 0; nt < 4; nt++) {
        const int col = colN + warpN * 32 + nt * 8 + 2 * t;
        bb[nt][0] = __ldg(bias + col);
        bb[nt][1] = __ldg(bias + col + 1);
    }
    if (mode == 0) {
        float* Cf = (float*)C;
        #pragma unroll
        for (int mt = 0; mt < 2; mt++) {
            const int r0_ = rowM + warpM * 32 + mt * 16 + g;
            #pragma unroll
            for (int nt = 0; nt < 4; nt++) {
                const int col = colN + warpN * 32 + nt * 8 + 2 * t;
                float2 v0, v1;
                v0.x = acc[mt][nt][0] + bb[nt][0];
                v0.y = acc[mt][nt][1] + bb[nt][1];
                v1.x = acc[mt][nt][2] + bb[nt][0];
                v1.y = acc[mt][nt][3] + bb[nt][1];
                *(float2*)(Cf + (size_t)r0_ * N + col)       = v0;
                *(float2*)(Cf + (size_t)(r0_ + 8) * N + col) = v1;
            }
        }
    } else {
        __half* Ch = (__half*)C;
        const float sc = (mode == 3) ? QSCALE : 1.0f;
        #pragma unroll
        for (int mt = 0; mt < 2; mt++) {
            const int r0_ = rowM + warpM * 32 + mt * 16 + g;
            #pragma unroll
            for (int nt = 0; nt < 4; nt++) {
                const int col = colN + warpN * 32 + nt * 8 + 2 * t;
                *(__half2*)(Ch + (size_t)r0_ * N + col) =
                    __floats2half2_rn((acc[mt][nt][0] + bb[nt][0]) * sc,
                                      (acc[mt][nt][1] + bb[nt][1]) * sc);
                *(__half2*)(Ch + (size_t)(r0_ + 8) * N + col) =
                    __floats2half2_rn((acc[mt][nt][2] + bb[nt][0]) * sc,
                                      (acc[mt][nt][3] + bb[nt][1]) * sc);
            }
        }
    }
}

// ---------------------------------------------------------------------------
// fp16 flash attention, FA-2 register P; V in standard [B,S,HID] layout,
// transposed in-flight via ldmatrix.trans (no transposed epilogue needed).
// smem: two K+V buffers (each K 64x144B then V 64x144B). Q stages via buf1.
// ---------------------------------------------------------------------------
#define BQ 128
#define BK 64
#define PITCHB 144                         // 72 halfs per row
#define KVBUF_B (2 * BK * PITCHB)          // 18432 B
#define ATTN_SMEM (2 * KVBUF_B)            // 36864 B

__global__ void __launch_bounds__(256, 2)
attn_tc(const __half* __restrict__ Q, const __half* __restrict__ Kg_,
        const __half* __restrict__ Vg_, __half* __restrict__ O)
{
    extern __shared__ char smc[];

    const int tid  = threadIdx.x;
    const int wid  = tid >> 5;
    const int lane = tid & 31;
    const int g    = lane >> 2;
    const int t    = lane & 3;
    const int bh   = blockIdx.y;
    const int b    = bh / NH_;
    const int h    = bh % NH_;
    const int q0   = blockIdx.x * BQ;

    const uint32_t uB0 = smem_u32(smc);
    const uint32_t uB1 = uB0 + KVBUF_B;

    const int a_row = lane & 15;
    const int a_u   = lane >> 4;
    const int b_row = ((lane >> 4) & 1) * 8 + (lane & 7);
    const int b_u   = (lane >> 3) & 1;
    // trans-V lane map: row-8 selector from lane>>3, unit selector from lane>>4
    const int v_row = ((lane >> 3) & 1) * 8 + (lane & 7);
    const int v_u   = (lane >> 4) & 1;

    const __half* Kg = Kg_ + (size_t)(b * S_) * HID_ + h * HD_;
    const __half* Vg = Vg_ + (size_t)(b * S_) * HID_ + h * HD_;

    const int lr = tid >> 2;            // 0..63 key row
    const int lu = (tid & 3) * 2;       // 16B units 0,2,4,6

    // ---- issue tile 0 K/V into buf0 ----
    {
        const uint32_t dk = uB0 + (uint32_t)(lr * PITCHB + lu * 16);
        const uint32_t dv = dk + (uint32_t)(BK * PITCHB);
        const __half* ks = Kg + (size_t)lr * HID_ + lu * 8;
        const __half* vs = Vg + (size_t)lr * HID_ + lu * 8;
        #pragma unroll
        for (int i = 0; i < 2; i++) {
            CPA16(dk + i * 16, ks + i * 8);
            CPA16(dv + i * 16, vs + i * 8);
        }
        CPA_COMMIT();
    }

    // ---- stage Q (pre-scaled fp16) into buf1 via cp.async ----
    {
        const int qr = tid >> 1;
        const int qu = (tid & 1) * 4;
        const uint32_t dq = uB1 + (uint32_t)(qr * PITCHB + qu * 16);
        const __half* qs = Q + (size_t)(b * S_ + q0 + qr) * HID_ + h * HD_ + qu * 8;
        #pragma unroll
        for (int i = 0; i < 4; i++) CPA16(dq + i * 16, qs + i * 8);
        CPA_COMMIT();
    }
    CPA_WAIT0();
    __syncthreads();

    uint32_t qf[4][4];
    #pragma unroll
    for (int kc = 0; kc < 4; kc++)
        ldmatrix_x4(qf[kc][0], qf[kc][1], qf[kc][2], qf[kc][3],
            uB1 + (uint32_t)((wid * 16 + a_row) * PITCHB + (kc * 2 + a_u) * 16));
    __syncthreads();

    float o[8][4];
    #pragma unroll
    for (int nt = 0; nt < 8; nt++)
        #pragma unroll
        for (int q = 0; q < 4; q++) o[nt][q] = 0.0f;
    float m0 = -1e30f, m1 = -1e30f, l0 = 0.0f, l1 = 0.0f;

    const int NT = S_ / BK;   // 32

    for (int kt = 0; kt < NT; kt++) {
        const uint32_t uKb = (kt & 1) ? uB1 : uB0;
        const uint32_t uVb = uKb + (uint32_t)(BK * PITCHB);

        if (kt + 1 < NT) {
            const uint32_t dst = (kt & 1) ? uB0 : uB1;
            const uint32_t dk = dst + (uint32_t)(lr * PITCHB + lu * 16);
            const uint32_t dv = dk + (uint32_t)(BK * PITCHB);
            const __half* ks = Kg + (size_t)((kt + 1) * BK + lr) * HID_ + lu * 8;
            const __half* vs = Vg + (size_t)((kt + 1) * BK + lr) * HID_ + lu * 8;
            #pragma unroll
            for (int i = 0; i < 2; i++) {
                CPA16(dk + i * 16, ks + i * 8);
                CPA16(dv + i * 16, vs + i * 8);
            }
            CPA_COMMIT();
            CPA_WAIT1();
        } else {
            CPA_WAIT0();
        }
        __syncthreads();

        // ---- S = Q @ K^T (4 k16 steps) ----
        float s[8][4];
        #pragma unroll
        for (int nt = 0; nt < 8; nt++)
            #pragma unroll
            for (int q = 0; q < 4; q++) s[nt][q] = 0.0f;

        #pragma unroll
        for (int kc = 0; kc < 4; kc++) {
            uint32_t bf[8][2];
            #pragma unroll
            for (int nb = 0; nb < 4; nb++) {
                uint32_t r0, r1, r2, r3;
                ldmatrix_x4(r0, r1, r2, r3,
                    uKb + (uint32_t)((nb * 16 + b_row) * PITCHB + (kc * 2 + b_u) * 16));
                bf[nb * 2 + 0][0] = r0; bf[nb * 2 + 0][1] = r1;
                bf[nb * 2 + 1][0] = r2; bf[nb * 2 + 1][1] = r3;
            }
            #pragma unroll
            for (int nt = 0; nt < 8; nt++)
                mma_f16(s[nt][0], s[nt][1], s[nt][2], s[nt][3],
                        qf[kc][0], qf[kc][1], qf[kc][2], qf[kc][3],
                        bf[nt][0], bf[nt][1]);
        }

        // ---- online softmax; P stays in registers ----
        float mx0 = -1e30f, mx1 = -1e30f;
        #pragma unroll
        for (int nt = 0; nt < 8; nt++) {
            mx0 = fmaxf(mx0, fmaxf(s[nt][0], s[nt][1]));
            mx1 = fmaxf(mx1, fmaxf(s[nt][2], s[nt][3]));
        }
        mx0 = quad_max(mx0); mx1 = quad_max(mx1);
        const float mn0 = fmaxf(m0, mx0);
        const float mn1 = fmaxf(m1, mx1);
        const float c0r = exp2f(m0 - mn0);
        const float c1r = exp2f(m1 - mn1);
        m0 = mn0; m1 = mn1;

        uint32_t ph[8][2];
        float sum0 = 0.0f, sum1 = 0.0f;
        #pragma unroll
        for (int nt = 0; nt < 8; nt++) {
            float p0 = exp2f(s[nt][0] - mn0);
            float p1 = exp2f(s[nt][1] - mn0);
            float p2 = exp2f(s[nt][2] - mn1);
            float p3 = exp2f(s[nt][3] - mn1);
            sum0 += p0 + p1;
            sum1 += p2 + p3;
            o[nt][0] *= c0r; o[nt][1] *= c0r;
            o[nt][2] *= c1r; o[nt][3] *= c1r;
            __half2 h01 = __floats2half2_rn(p0, p1);
            __half2 h23 = __floats2half2_rn(p2, p3);
            ph[nt][0] = *(uint32_t*)&h01;
            ph[nt][1] = *(uint32_t*)&h23;
        }
        sum0 = quad_sum(sum0); sum1 = quad_sum(sum1);
        l0 = l0 * c0r + sum0;
        l1 = l1 * c1r + sum1;

        // ---- O += P @ V (V transposed in-flight via ldmatrix.trans) ----
        #pragma unroll
        for (int kc = 0; kc < 4; kc++) {
            uint32_t vf[8][2];
            #pragma unroll
            for (int nb = 0; nb < 4; nb++) {
                uint32_t r0, r1, r2, r3;
                ldmatrix_x4_trans(r0, r1, r2, r3,
                    uVb + (uint32_t)((kc * 16 + v_row) * PITCHB + (nb * 2 + v_u) * 16));
                vf[nb * 2 + 0][0] = r0; vf[nb * 2 + 0][1] = r1;
                vf[nb * 2 + 1][0] = r2; vf[nb * 2 + 1][1] = r3;
            }
            #pragma unroll
            for (int nt = 0; nt < 8; nt++)
                mma_f16(o[nt][0], o[nt][1], o[nt][2], o[nt][3],
                        ph[2 * kc][0], ph[2 * kc][1],
                        ph[2 * kc + 1][0], ph[2 * kc + 1][1],
                        vf[nt][0], vf[nt][1]);
        }
        __syncthreads();
    }

    const float inv0 = 1.0f / l0;
    const float inv1 = 1.0f / l1;
    __half* Or = O + (size_t)(b * S_ + q0 + wid * 16 + g) * HID_ + h * HD_;
    #pragma unroll
    for (int nt = 0; nt < 8; nt++) {
        *(__half2*)(Or + nt * 8 + 2 * t) =
            __floats2half2_rn(o[nt][0] * inv0, o[nt][1] * inv0);
        *(__half2*)(Or + 8 * HID_ + nt * 8 + 2 * t) =
            __floats2half2_rn(o[nt][2] * inv1, o[nt][3] * inv1);
    }
}

// ---------------------------------------------------------------------------
// Launch
// ---------------------------------------------------------------------------
extern "C" void kernel_launch(void* const* d_in, const int* in_sizes, int n_in,
                              void* d_out, int out_size)
{
    const float* x  = (const float*)d_in[0];
    const float* Wq = (const float*)d_in[1];
    const float* bq = (const float*)d_in[2];
    const float* Wk = (const float*)d_in[3];
    const float* bk = (const float*)d_in[4];
    const float* Wv = (const float*)d_in[5];
    const float* bv = (const float*)d_in[6];
    const float* Wo = (const float*)d_in[7];
    const float* bo = (const float*)d_in[8];
    float* out = (float*)d_out;

    __half *qp, *kp, *vp, *ap, *xt, *wt, *wo;
    cudaGetSymbolAddress((void**)&qp, g_q);
    cudaGetSymbolAddress((void**)&kp, g_k);
    cudaGetSymbolAddress((void**)&vp, g_v);
    cudaGetSymbolAddress((void**)&ap, g_attn);
    cudaGetSymbolAddress((void**)&xt, g_xt);
    cudaGetSymbolAddress((void**)&wt, g_wt);
    cudaGetSymbolAddress((void**)&wo, g_wo);

    cudaFuncSetAttribute(gemm_tc, cudaFuncAttributeMaxDynamicSharedMemorySize,
                         GEMM_SMEM);
    cudaFuncSetAttribute(attn_tc, cudaFuncAttributeMaxDynamicSharedMemorySize,
                         ATTN_SMEM);

    // 0) convert inputs/weights to fp16
    {
        const int NX4 = MTOT * HID_ / 4;
        const int NW4 = HID_ * HID_ / 4;
        to_half<<<NX4 / 256, 256>>>(x, xt, NX4);
        dim3 wg(NW4 / 256, 1, 4);
        to_half_w4<<<wg, 256>>>(Wq, Wk, Wv, Wo,
                                wt, wt + HID_ * HID_, wt + 2 * HID_ * HID_, wo,
                                NW4);
    }

    // 1) fused QKV projections: q scaled (mode 3), k fp16 (1), v fp16 (1)
    {
        dim3 grid(HID_ / 128, MTOT / 128, 3);
        gemm_tc<<<grid, 512, GEMM_SMEM>>>(xt, wt, wt + HID_ * HID_,
                                          wt + 2 * HID_ * HID_,
                                          bq, bk, bv,
                                          (void*)qp, (void*)kp, (void*)vp,
                                          MTOT, HID_, HID_, 3, 1, 1);
    }

    // 2) attention (fp16 m16n8k16, register-P, ldmatrix.trans V)
    {
        dim3 grid(S_ / BQ, B_ * NH_);
        attn_tc<<<grid, 256, ATTN_SMEM>>>(qp, kp, vp, ap);
    }

    // 3) output projection (fp32 out)
    {
        dim3 grid(HID_ / 128, MTOT / 128, 1);
        gemm_tc<<<grid, 512, GEMM_SMEM>>>(ap, wo, wo, wo, bo, bo, bo,
                                          (void*)out, (void*)out, (void*)out,
                                          MTOT, HID_, HID_, 0, 0, 0);
    }
}

// round 14
// speedup vs baseline: 1.0434x; 1.0217x over previous
#include <cuda_runtime.h>
#include <cuda_fp16.h>
#include <cstdint>
#include <math.h>

#define B_   2
#define S_   2048
#define HID_ 1024
#define NH_  16
#define HD_  64
#define MTOT (B_ * S_)   // 4096
#define QSCALE 0.1803368801111204f      // 0.125 * log2(e)

// ---------------------------------------------------------------------------
// Scratch buffers (no cudaMalloc allowed). All fp16, standard layouts.
// ---------------------------------------------------------------------------
__device__ __half g_q[MTOT * HID_];
__device__ __half g_k[MTOT * HID_];
__device__ __half g_v[MTOT * HID_];
__device__ __half g_attn[MTOT * HID_];
__device__ __half g_xt[MTOT * HID_];
__device__ __half g_wt[3 * HID_ * HID_];
__device__ __half g_wo[HID_ * HID_];

// ---------------------------------------------------------------------------
// Helpers
// ---------------------------------------------------------------------------
__device__ __forceinline__ uint32_t smem_u32(const void* p) {
    uint32_t a;
    asm("{ .reg .u64 t; cvta.to.shared.u64 t, %1; cvt.u32.u64 %0, t; }"
        : "=r"(a) : "l"(p));
    return a;
}

__device__ __forceinline__ void ldmatrix_x4(uint32_t& r0, uint32_t& r1,
                                            uint32_t& r2, uint32_t& r3,
                                            uint32_t addr) {
    asm volatile("ldmatrix.sync.aligned.m8n8.x4.shared.b16 {%0,%1,%2,%3}, [%4];"
                 : "=r"(r0), "=r"(r1), "=r"(r2), "=r"(r3) : "r"(addr));
}

__device__ __forceinline__ void ldmatrix_x4_trans(uint32_t& r0, uint32_t& r1,
                                                  uint32_t& r2, uint32_t& r3,
                                                  uint32_t addr) {
    asm volatile("ldmatrix.sync.aligned.m8n8.x4.trans.shared.b16 {%0,%1,%2,%3}, [%4];"
                 : "=r"(r0), "=r"(r1), "=r"(r2), "=r"(r3) : "r"(addr));
}

__device__ __forceinline__ void mma_f16(float& c0, float& c1, float& c2, float& c3,
                                        uint32_t a0, uint32_t a1, uint32_t a2,
                                        uint32_t a3, uint32_t b0, uint32_t b1) {
    asm volatile(
        "mma.sync.aligned.m16n8k16.row.col.f32.f16.f16.f32 "
        "{%0,%1,%2,%3}, {%4,%5,%6,%7}, {%8,%9}, {%0,%1,%2,%3};"
        : "+f"(c0), "+f"(c1), "+f"(c2), "+f"(c3)
        : "r"(a0), "r"(a1), "r"(a2), "r"(a3), "r"(b0), "r"(b1));
}

__device__ __forceinline__ float quad_max(float v) {
    v = fmaxf(v, __shfl_xor_sync(0xffffffffu, v, 1));
    v = fmaxf(v, __shfl_xor_sync(0xffffffffu, v, 2));
    return v;
}
__device__ __forceinline__ float quad_sum(float v) {
    v += __shfl_xor_sync(0xffffffffu, v, 1);
    v += __shfl_xor_sync(0xffffffffu, v, 2);
    return v;
}

#define CPA16(dst, src) \
    asm volatile("cp.async.cg.shared.global [%0], [%1], 16;" \
                 :: "r"(dst), "l"(src) : "memory")
#define CPA_COMMIT() asm volatile("cp.async.commit_group;" ::: "memory")
#define CPA_WAIT2()  asm volatile("cp.async.wait_group 2;" ::: "memory")
#define CPA_WAIT1()  asm volatile("cp.async.wait_group 1;" ::: "memory")
#define CPA_WAIT0()  asm volatile("cp.async.wait_group 0;" ::: "memory")

// ---------------------------------------------------------------------------
// fp32 -> fp16 conversion passes
// ---------------------------------------------------------------------------
__global__ void __launch_bounds__(256)
to_half(const float* __restrict__ in, __half* __restrict__ out, int n4)
{
    int i = blockIdx.x * 256 + threadIdx.x;
    if (i < n4) {
        float4 v = ((const float4*)in)[i];
        __half2* o = (__half2*)(out + 4 * (size_t)i);
        o[0] = __floats2half2_rn(v.x, v.y);
        o[1] = __floats2half2_rn(v.z, v.w);
    }
}

__global__ void __launch_bounds__(256)
to_half_w4(const float* __restrict__ w0, const float* __restrict__ w1,
           const float* __restrict__ w2, const float* __restrict__ w3,
           __half* __restrict__ o0, __half* __restrict__ o1,
           __half* __restrict__ o2, __half* __restrict__ o3, int n4)
{
    const float* in; __half* out;
    if (blockIdx.z == 0)      { in = w0; out = o0; }
    else if (blockIdx.z == 1) { in = w1; out = o1; }
    else if (blockIdx.z == 2) { in = w2; out = o2; }
    else                      { in = w3; out = o3; }
    int i = blockIdx.x * 256 + threadIdx.x;
    if (i < n4) {
        float4 v = ((const float4*)in)[i];
        __half2* o = (__half2*)(out + 4 * (size_t)i);
        o[0] = __floats2half2_rn(v.x, v.y);
        o[1] = __floats2half2_rn(v.z, v.w);
    }
}

// ---------------------------------------------------------------------------
// fp16 mma.sync GEMM (m16n8k16), cp.async 4-stage pipeline, 512 threads
// (16 warps 4x4), CTA tile 256x128x64, warp tile 64x32.
//   C[M,N] = A[M,K] @ W[N,K]^T + bias[N]      (A, W fp16, fp32 accum)
// Stage = A 32KB (256 rows) + B 16KB (128 rows); 4 stages = 192KB smem.
// mode: 0 fp32 store; 1 fp16 store; 3 fp16 store scaled by QSCALE (Q).
// ---------------------------------------------------------------------------
#define STAGE_BYTES 49152
#define GEMM_SMEM (4 * STAGE_BYTES)        // 196608

__global__ void __launch_bounds__(512)
gemm_tc(const __half* __restrict__ A,
        const __half* __restrict__ W0, const __half* __restrict__ W1,
        const __half* __restrict__ W2,
        const float* __restrict__ b0_, const float* __restrict__ b1_,
        const float* __restrict__ b2_,
        void* __restrict__ C0, void* __restrict__ C1, void* __restrict__ C2,
        int M, int N, int K, int mode0, int mode1, int mode2)
{
    extern __shared__ char smc[];
    const uint32_t sbase = smem_u32(smc);
    const int tid  = threadIdx.x;
    const int wid  = tid >> 5;
    const int lane = tid & 31;
    const int warpM = wid & 3;          // 4 warp-rows (64 rows each)
    const int warpN = wid >> 2;         // 4 warp-cols (32 cols each)

    const __half* W; const float* bias; void* C; int mode;
    if (blockIdx.z == 0)      { W = W0; bias = b0_; C = C0; mode = mode0; }
    else if (blockIdx.z == 1) { W = W1; bias = b1_; C = C1; mode = mode1; }
    else                      { W = W2; bias = b2_; C = C2; mode = mode2; }

    const int rowM = blockIdx.y * 256;
    const int colN = blockIdx.x * 128;
    const __half* Ag = A + (size_t)rowM * K;
    const __half* Wg = W + (size_t)colN * K;

    // cp.async maps: A 256 rows x 8 units (4/thread); B 128 rows x 8 units (2/thread)
    const int ar = tid >> 1;            // 0..255
    const int au = (tid & 1) * 4;       // 0 or 4
    const int br = tid >> 2;            // 0..127
    const int bu = (tid & 3) * 2;       // 0,2,4,6
    const __half* agr = Ag + (size_t)ar * K;
    const __half* wgr = Wg + (size_t)br * K;

    const int a_row = lane & 15;
    const int a_u   = lane >> 4;
    const int b_row = ((lane >> 4) & 1) * 8 + (lane & 7);
    const int b_u   = (lane >> 3) & 1;

    float acc[4][4][4];
    #pragma unroll
    for (int mt = 0; mt < 4; mt++)
        #pragma unroll
        for (int nt = 0; nt < 4; nt++)
            #pragma unroll
            for (int q = 0; q < 4; q++) acc[mt][nt][q] = 0.0f;

    const int NC = K / 64;               // 16 chunks

    #pragma unroll
    for (int s = 0; s < 3; s++) {
        const uint32_t sa = sbase + s * STAGE_BYTES + ar * 128;
        const uint32_t sb = sbase + s * STAGE_BYTES + 32768 + br * 128;
        const __half* ac = agr + s * 64;
        const __half* wc = wgr + s * 64;
        #pragma unroll
        for (int i = 0; i < 4; i++) {
            const int u = au + i;
            CPA16(sa + (uint32_t)((u ^ (ar & 7)) << 4), ac + u * 8);
        }
        #pragma unroll
        for (int i = 0; i < 2; i++) {
            const int u = bu + i;
            CPA16(sb + (uint32_t)((u ^ (br & 7)) << 4), wc + u * 8);
        }
        CPA_COMMIT();
    }

    for (int c = 0; c < NC; c++) {
        const int buf = c & 3;
        CPA_WAIT2();
        __syncthreads();

        if (c + 3 < NC) {
            const int s = (c + 3) & 3;
            const uint32_t sa = sbase + s * STAGE_BYTES + ar * 128;
            const uint32_t sb = sbase + s * STAGE_BYTES + 32768 + br * 128;
            const __half* ac = agr + (c + 3) * 64;
            const __half* wc = wgr + (c + 3) * 64;
            #pragma unroll
            for (int i = 0; i < 4; i++) {
                const int u = au + i;
                CPA16(sa + (uint32_t)((u ^ (ar & 7)) << 4), ac + u * 8);
            }
            #pragma unroll
            for (int i = 0; i < 2; i++) {
                const int u = bu + i;
                CPA16(sb + (uint32_t)((u ^ (br & 7)) << 4), wc + u * 8);
            }
        }
        CPA_COMMIT();

        const uint32_t stA = sbase + buf * STAGE_BYTES;
        const uint32_t stB = stA + 32768;
        #pragma unroll
        for (int kc = 0; kc < 4; kc++) {
            uint32_t af[4][4];
            #pragma unroll
            for (int mt = 0; mt < 4; mt++) {
                const int row = warpM * 64 + mt * 16 + a_row;
                const uint32_t addr = stA + (uint32_t)(row * 128) +
                    (uint32_t)((((kc * 2 + a_u) ^ (row & 7))) << 4);
                ldmatrix_x4(af[mt][0], af[mt][1], af[mt][2], af[mt][3], addr);
            }
            uint32_t bf[4][2];
            #pragma unroll
            for (int nb = 0; nb < 2; nb++) {
                const int row = warpN * 32 + nb * 16 + b_row;
                const uint32_t addr = stB + (uint32_t)(row * 128) +
                    (uint32_t)((((kc * 2 + b_u) ^ (row & 7))) << 4);
                uint32_t r0, r1, r2, r3;
                ldmatrix_x4(r0, r1, r2, r3, addr);
                bf[nb * 2 + 0][0] = r0; bf[nb * 2 + 0][1] = r1;
                bf[nb * 2 + 1][0] = r2; bf[nb * 2 + 1][1] = r3;
            }
            #pragma unroll
            for (int mt = 0; mt < 4; mt++)
                #pragma unroll
                for (int nt = 0; nt < 4; nt++)
                    mma_f16(acc[mt][nt][0], acc[mt][nt][1],
                            acc[mt][nt][2], acc[mt][nt][3],
                            af[mt][0], af[mt][1], af[mt][2], af[mt][3],
                            bf[nt][0], bf[nt][1]);
        }
    }

    const int g = lane >> 2;
    const int t = lane & 3;
    float bb[4][2];
    #pragma unroll
    for (int nt = 0; nt < 4; nt++) {
        const int col = colN + warpN * 32 + nt * 8 + 2 * t;
        bb[nt][0] = __ldg(bias + col);
        bb[nt][1] = __ldg(bias + col + 1);
    }
    if (mode == 0) {
        float* Cf = (float*)C;
        #pragma unroll
        for (int mt = 0; mt < 4; mt++) {
            const int r0_ = rowM + warpM * 64 + mt * 16 + g;
            #pragma unroll
            for (int nt = 0; nt < 4; nt++) {
                const int col = colN + warpN * 32 + nt * 8 + 2 * t;
                float2 v0, v1;
                v0.x = acc[mt][nt][0] + bb[nt][0];
                v0.y = acc[mt][nt][1] + bb[nt][1];
                v1.x = acc[mt][nt][2] + bb[nt][0];
                v1.y = acc[mt][nt][3] + bb[nt][1];
                *(float2*)(Cf + (size_t)r0_ * N + col)       = v0;
                *(float2*)(Cf + (size_t)(r0_ + 8) * N + col) = v1;
            }
        }
    } else {
        __half* Ch = (__half*)C;
        const float sc = (mode == 3) ? QSCALE : 1.0f;
        #pragma unroll
        for (int mt = 0; mt < 4; mt++) {
            const int r0_ = rowM + warpM * 64 + mt * 16 + g;
            #pragma unroll
            for (int nt = 0; nt < 4; nt++) {
                const int col = colN + warpN * 32 + nt * 8 + 2 * t;
                *(__half2*)(Ch + (size_t)r0_ * N + col) =
                    __floats2half2_rn((acc[mt][nt][0] + bb[nt][0]) * sc,
                                      (acc[mt][nt][1] + bb[nt][1]) * sc);
                *(__half2*)(Ch + (size_t)(r0_ + 8) * N + col) =
                    __floats2half2_rn((acc[mt][nt][2] + bb[nt][0]) * sc,
                                      (acc[mt][nt][3] + bb[nt][1]) * sc);
            }
        }
    }
}

// ---------------------------------------------------------------------------
// fp16 flash attention, FA-2 register P, ldmatrix.trans V.
// (unchanged from round 13 — 134.6us, protected)
// ---------------------------------------------------------------------------
#define BQ 128
#define BK 64
#define PITCHB 144                         // 72 halfs per row
#define KVBUF_B (2 * BK * PITCHB)          // 18432 B
#define ATTN_SMEM (2 * KVBUF_B)            // 36864 B

__global__ void __launch_bounds__(256, 2)
attn_tc(const __half* __restrict__ Q, const __half* __restrict__ Kg_,
        const __half* __restrict__ Vg_, __half* __restrict__ O)
{
    extern __shared__ char smc[];

    const int tid  = threadIdx.x;
    const int wid  = tid >> 5;
    const int lane = tid & 31;
    const int g    = lane >> 2;
    const int t    = lane & 3;
    const int bh   = blockIdx.y;
    const int b    = bh / NH_;
    const int h    = bh % NH_;
    const int q0   = blockIdx.x * BQ;

    const uint32_t uB0 = smem_u32(smc);
    const uint32_t uB1 = uB0 + KVBUF_B;

    const int a_row = lane & 15;
    const int a_u   = lane >> 4;
    const int b_row = ((lane >> 4) & 1) * 8 + (lane & 7);
    const int b_u   = (lane >> 3) & 1;
    const int v_row = ((lane >> 3) & 1) * 8 + (lane & 7);
    const int v_u   = (lane >> 4) & 1;

    const __half* Kg = Kg_ + (size_t)(b * S_) * HID_ + h * HD_;
    const __half* Vg = Vg_ + (size_t)(b * S_) * HID_ + h * HD_;

    const int lr = tid >> 2;            // 0..63 key row
    const int lu = (tid & 3) * 2;       // 16B units 0,2,4,6

    {
        const uint32_t dk = uB0 + (uint32_t)(lr * PITCHB + lu * 16);
        const uint32_t dv = dk + (uint32_t)(BK * PITCHB);
        const __half* ks = Kg + (size_t)lr * HID_ + lu * 8;
        const __half* vs = Vg + (size_t)lr * HID_ + lu * 8;
        #pragma unroll
        for (int i = 0; i < 2; i++) {
            CPA16(dk + i * 16, ks + i * 8);
            CPA16(dv + i * 16, vs + i * 8);
        }
        CPA_COMMIT();
    }

    {
        const int qr = tid >> 1;
        const int qu = (tid & 1) * 4;
        const uint32_t dq = uB1 + (uint32_t)(qr * PITCHB + qu * 16);
        const __half* qs = Q + (size_t)(b * S_ + q0 + qr) * HID_ + h * HD_ + qu * 8;
        #pragma unroll
        for (int i = 0; i < 4; i++) CPA16(dq + i * 16, qs + i * 8);
        CPA_COMMIT();
    }
    CPA_WAIT0();
    __syncthreads();

    uint32_t qf[4][4];
    #pragma unroll
    for (int kc = 0; kc < 4; kc++)
        ldmatrix_x4(qf[kc][0], qf[kc][1], qf[kc][2], qf[kc][3],
            uB1 + (uint32_t)((wid * 16 + a_row) * PITCHB + (kc * 2 + a_u) * 16));
    __syncthreads();

    float o[8][4];
    #pragma unroll
    for (int nt = 0; nt < 8; nt++)
        #pragma unroll
        for (int q = 0; q < 4; q++) o[nt][q] = 0.0f;
    float m0 = -1e30f, m1 = -1e30f, l0 = 0.0f, l1 = 0.0f;

    const int NT = S_ / BK;   // 32

    for (int kt = 0; kt < NT; kt++) {
        const uint32_t uKb = (kt & 1) ? uB1 : uB0;
        const uint32_t uVb = uKb + (uint32_t)(BK * PITCHB);

        if (kt + 1 < NT) {
            const uint32_t dst = (kt & 1) ? uB0 : uB1;
            const uint32_t dk = dst + (uint32_t)(lr * PITCHB + lu * 16);
            const uint32_t dv = dk + (uint32_t)(BK * PITCHB);
            const __half* ks = Kg + (size_t)((kt + 1) * BK + lr) * HID_ + lu * 8;
            const __half* vs = Vg + (size_t)((kt + 1) * BK + lr) * HID_ + lu * 8;
            #pragma unroll
            for (int i = 0; i < 2; i++) {
                CPA16(dk + i * 16, ks + i * 8);
                CPA16(dv + i * 16, vs + i * 8);
            }
            CPA_COMMIT();
            CPA_WAIT1();
        } else {
            CPA_WAIT0();
        }
        __syncthreads();

        float s[8][4];
        #pragma unroll
        for (int nt = 0; nt < 8; nt++)
            #pragma unroll
            for (int q = 0; q < 4; q++) s[nt][q] = 0.0f;

        #pragma unroll
        for (int kc = 0; kc < 4; kc++) {
            uint32_t bf[8][2];
            #pragma unroll
            for (int nb = 0; nb < 4; nb++) {
                uint32_t r0, r1, r2, r3;
                ldmatrix_x4(r0, r1, r2, r3,
                    uKb + (uint32_t)((nb * 16 + b_row) * PITCHB + (kc * 2 + b_u) * 16));
                bf[nb * 2 + 0][0] = r0; bf[nb * 2 + 0][1] = r1;
                bf[nb * 2 + 1][0] = r2; bf[nb * 2 + 1][1] = r3;
            }
            #pragma unroll
            for (int nt = 0; nt < 8; nt++)
                mma_f16(s[nt][0], s[nt][1], s[nt][2], s[nt][3],
                        qf[kc][0], qf[kc][1], qf[kc][2], qf[kc][3],
                        bf[nt][0], bf[nt][1]);
        }

        float mx0 = -1e30f, mx1 = -1e30f;
        #pragma unroll
        for (int nt = 0; nt < 8; nt++) {
            mx0 = fmaxf(mx0, fmaxf(s[nt][0], s[nt][1]));
            mx1 = fmaxf(mx1, fmaxf(s[nt][2], s[nt][3]));
        }
        mx0 = quad_max(mx0); mx1 = quad_max(mx1);
        const float mn0 = fmaxf(m0, mx0);
        const float mn1 = fmaxf(m1, mx1);
        const float c0r = exp2f(m0 - mn0);
        const float c1r = exp2f(m1 - mn1);
        m0 = mn0; m1 = mn1;

        uint32_t ph[8][2];
        float sum0 = 0.0f, sum1 = 0.0f;
        #pragma unroll
        for (int nt = 0; nt < 8; nt++) {
            float p0 = exp2f(s[nt][0] - mn0);
            float p1 = exp2f(s[nt][1] - mn0);
            float p2 = exp2f(s[nt][2] - mn1);
            float p3 = exp2f(s[nt][3] - mn1);
            sum0 += p0 + p1;
            sum1 += p2 + p3;
            o[nt][0] *= c0r; o[nt][1] *= c0r;
            o[nt][2] *= c1r; o[nt][3] *= c1r;
            __half2 h01 = __floats2half2_rn(p0, p1);
            __half2 h23 = __floats2half2_rn(p2, p3);
            ph[nt][0] = *(uint32_t*)&h01;
            ph[nt][1] = *(uint32_t*)&h23;
        }
        sum0 = quad_sum(sum0); sum1 = quad_sum(sum1);
        l0 = l0 * c0r + sum0;
        l1 = l1 * c1r + sum1;

        #pragma unroll
        for (int kc = 0; kc < 4; kc++) {
            uint32_t vf[8][2];
            #pragma unroll
            for (int nb = 0; nb < 4; nb++) {
                uint32_t r0, r1, r2, r3;
                ldmatrix_x4_trans(r0, r1, r2, r3,
                    uVb + (uint32_t)((kc * 16 + v_row) * PITCHB + (nb * 2 + v_u) * 16));
                vf[nb * 2 + 0][0] = r0; vf[nb * 2 + 0][1] = r1;
                vf[nb * 2 + 1][0] = r2; vf[nb * 2 + 1][1] = r3;
            }
            #pragma unroll
            for (int nt = 0; nt < 8; nt++)
                mma_f16(o[nt][0], o[nt][1], o[nt][2], o[nt][3],
                        ph[2 * kc][0], ph[2 * kc][1],
                        ph[2 * kc + 1][0], ph[2 * kc + 1][1],
                        vf[nt][0], vf[nt][1]);
        }
        __syncthreads();
    }

    const float inv0 = 1.0f / l0;
    const float inv1 = 1.0f / l1;
    __half* Or = O + (size_t)(b * S_ + q0 + wid * 16 + g) * HID_ + h * HD_;
    #pragma unroll
    for (int nt = 0; nt < 8; nt++) {
        *(__half2*)(Or + nt * 8 + 2 * t) =
            __floats2half2_rn(o[nt][0] * inv0, o[nt][1] * inv0);
        *(__half2*)(Or + 8 * HID_ + nt * 8 + 2 * t) =
            __floats2half2_rn(o[nt][2] * inv1, o[nt][3] * inv1);
    }
}

// ---------------------------------------------------------------------------
// Launch
// ---------------------------------------------------------------------------
extern "C" void kernel_launch(void* const* d_in, const int* in_sizes, int n_in,
                              void* d_out, int out_size)
{
    const float* x  = (const float*)d_in[0];
    const float* Wq = (const float*)d_in[1];
    const float* bq = (const float*)d_in[2];
    const float* Wk = (const float*)d_in[3];
    const float* bk = (const float*)d_in[4];
    const float* Wv = (const float*)d_in[5];
    const float* bv = (const float*)d_in[6];
    const float* Wo = (const float*)d_in[7];
    const float* bo = (const float*)d_in[8];
    float* out = (float*)d_out;

    __half *qp, *kp, *vp, *ap, *xt, *wt, *wo;
    cudaGetSymbolAddress((void**)&qp, g_q);
    cudaGetSymbolAddress((void**)&kp, g_k);
    cudaGetSymbolAddress((void**)&vp, g_v);
    cudaGetSymbolAddress((void**)&ap, g_attn);
    cudaGetSymbolAddress((void**)&xt, g_xt);
    cudaGetSymbolAddress((void**)&wt, g_wt);
    cudaGetSymbolAddress((void**)&wo, g_wo);

    cudaFuncSetAttribute(gemm_tc, cudaFuncAttributeMaxDynamicSharedMemorySize,
                         GEMM_SMEM);
    cudaFuncSetAttribute(attn_tc, cudaFuncAttributeMaxDynamicSharedMemorySize,
                         ATTN_SMEM);

    // 0) convert inputs/weights to fp16
    {
        const int NX4 = MTOT * HID_ / 4;
        const int NW4 = HID_ * HID_ / 4;
        to_half<<<NX4 / 256, 256>>>(x, xt, NX4);
        dim3 wg(NW4 / 256, 1, 4);
        to_half_w4<<<wg, 256>>>(Wq, Wk, Wv, Wo,
                                wt, wt + HID_ * HID_, wt + 2 * HID_ * HID_, wo,
                                NW4);
    }

    // 1) fused QKV projections: q scaled (mode 3), k fp16 (1), v fp16 (1)
    {
        dim3 grid(HID_ / 128, MTOT / 256, 3);
        gemm_tc<<<grid, 512, GEMM_SMEM>>>(xt, wt, wt + HID_ * HID_,
                                          wt + 2 * HID_ * HID_,
                                          bq, bk, bv,
                                          (void*)qp, (void*)kp, (void*)vp,
                                          MTOT, HID_, HID_, 3, 1, 1);
    }

    // 2) attention (fp16 m16n8k16, register-P, ldmatrix.trans V)
    {
        dim3 grid(S_ / BQ, B_ * NH_);
        attn_tc<<<grid, 256, ATTN_SMEM>>>(qp, kp, vp, ap);
    }

    // 3) output projection (fp32 out)
    {
        dim3 grid(HID_ / 128, MTOT / 256, 1);
        gemm_tc<<<grid, 512, GEMM_SMEM>>>(ap, wo, wo, wo, bo, bo, bo,
                                          (void*)out, (void*)out, (void*)out,
                                          MTOT, HID_, HID_, 0, 0, 0);
    }
}

// round 15
// speedup vs baseline: 1.0447x; 1.0013x over previous
#include <cuda_runtime.h>
#include <cuda_fp16.h>
#include <cstdint>
#include <math.h>

#define B_   2
#define S_   2048
#define HID_ 1024
#define NH_  16
#define HD_  64
#define MTOT (B_ * S_)   // 4096
#define QSCALE 0.1803368801111204f      // 0.125 * log2(e)

// ---------------------------------------------------------------------------
// Scratch buffers (no cudaMalloc allowed). All fp16, standard layouts.
// ---------------------------------------------------------------------------
__device__ __half g_q[MTOT * HID_];
__device__ __half g_k[MTOT * HID_];
__device__ __half g_v[MTOT * HID_];
__device__ __half g_attn[MTOT * HID_];
__device__ __half g_xt[MTOT * HID_];
__device__ __half g_wt[3 * HID_ * HID_];
__device__ __half g_wo[HID_ * HID_];

// ---------------------------------------------------------------------------
// Helpers
// ---------------------------------------------------------------------------
__device__ __forceinline__ uint32_t smem_u32(const void* p) {
    uint32_t a;
    asm("{ .reg .u64 t; cvta.to.shared.u64 t, %1; cvt.u32.u64 %0, t; }"
        : "=r"(a) : "l"(p));
    return a;
}

__device__ __forceinline__ float ex2(float x) {
    float y;
    asm("ex2.approx.f32 %0, %1;" : "=f"(y) : "f"(x));
    return y;
}

__device__ __forceinline__ void ldmatrix_x4(uint32_t& r0, uint32_t& r1,
                                            uint32_t& r2, uint32_t& r3,
                                            uint32_t addr) {
    asm volatile("ldmatrix.sync.aligned.m8n8.x4.shared.b16 {%0,%1,%2,%3}, [%4];"
                 : "=r"(r0), "=r"(r1), "=r"(r2), "=r"(r3) : "r"(addr));
}

__device__ __forceinline__ void ldmatrix_x4_trans(uint32_t& r0, uint32_t& r1,
                                                  uint32_t& r2, uint32_t& r3,
                                                  uint32_t addr) {
    asm volatile("ldmatrix.sync.aligned.m8n8.x4.trans.shared.b16 {%0,%1,%2,%3}, [%4];"
                 : "=r"(r0), "=r"(r1), "=r"(r2), "=r"(r3) : "r"(addr));
}

__device__ __forceinline__ void mma_f16(float& c0, float& c1, float& c2, float& c3,
                                        uint32_t a0, uint32_t a1, uint32_t a2,
                                        uint32_t a3, uint32_t b0, uint32_t b1) {
    asm volatile(
        "mma.sync.aligned.m16n8k16.row.col.f32.f16.f16.f32 "
        "{%0,%1,%2,%3}, {%4,%5,%6,%7}, {%8,%9}, {%0,%1,%2,%3};"
        : "+f"(c0), "+f"(c1), "+f"(c2), "+f"(c3)
        : "r"(a0), "r"(a1), "r"(a2), "r"(a3), "r"(b0), "r"(b1));
}

__device__ __forceinline__ float quad_max(float v) {
    v = fmaxf(v, __shfl_xor_sync(0xffffffffu, v, 1));
    v = fmaxf(v, __shfl_xor_sync(0xffffffffu, v, 2));
    return v;
}
__device__ __forceinline__ float quad_sum(float v) {
    v += __shfl_xor_sync(0xffffffffu, v, 1);
    v += __shfl_xor_sync(0xffffffffu, v, 2);
    return v;
}

#define CPA16(dst, src) \
    asm volatile("cp.async.cg.shared.global [%0], [%1], 16;" \
                 :: "r"(dst), "l"(src) : "memory")
#define CPA_COMMIT() asm volatile("cp.async.commit_group;" ::: "memory")
#define CPA_WAIT2()  asm volatile("cp.async.wait_group 2;" ::: "memory")
#define CPA_WAIT1()  asm volatile("cp.async.wait_group 1;" ::: "memory")
#define CPA_WAIT0()  asm volatile("cp.async.wait_group 0;" ::: "memory")

// ---------------------------------------------------------------------------
// fp32 -> fp16 conversion passes
// ---------------------------------------------------------------------------
__global__ void __launch_bounds__(256)
to_half(const float* __restrict__ in, __half* __restrict__ out, int n4)
{
    int i = blockIdx.x * 256 + threadIdx.x;
    if (i < n4) {
        float4 v = ((const float4*)in)[i];
        __half2* o = (__half2*)(out + 4 * (size_t)i);
        o[0] = __floats2half2_rn(v.x, v.y);
        o[1] = __floats2half2_rn(v.z, v.w);
    }
}

__global__ void __launch_bounds__(256)
to_half_w4(const float* __restrict__ w0, const float* __restrict__ w1,
           const float* __restrict__ w2, const float* __restrict__ w3,
           __half* __restrict__ o0, __half* __restrict__ o1,
           __half* __restrict__ o2, __half* __restrict__ o3, int n4)
{
    const float* in; __half* out;
    if (blockIdx.z == 0)      { in = w0; out = o0; }
    else if (blockIdx.z == 1) { in = w1; out = o1; }
    else if (blockIdx.z == 2) { in = w2; out = o2; }
    else                      { in = w3; out = o3; }
    int i = blockIdx.x * 256 + threadIdx.x;
    if (i < n4) {
        float4 v = ((const float4*)in)[i];
        __half2* o = (__half2*)(out + 4 * (size_t)i);
        o[0] = __floats2half2_rn(v.x, v.y);
        o[1] = __floats2half2_rn(v.z, v.w);
    }
}

// ---------------------------------------------------------------------------
// fp16 mma.sync GEMM (m16n8k16), cp.async 4-stage pipeline, 512 threads
// (16 warps 4x4), CTA tile 256x128x64, warp tile 64x32.  (round-14 proven)
// mode: 0 fp32 store; 1 fp16 store; 3 fp16 store scaled by QSCALE (Q).
// ---------------------------------------------------------------------------
#define STAGE_BYTES 49152
#define GEMM_SMEM (4 * STAGE_BYTES)        // 196608

__global__ void __launch_bounds__(512)
gemm_tc(const __half* __restrict__ A,
        const __half* __restrict__ W0, const __half* __restrict__ W1,
        const __half* __restrict__ W2,
        const float* __restrict__ b0_, const float* __restrict__ b1_,
        const float* __restrict__ b2_,
        void* __restrict__ C0, void* __restrict__ C1, void* __restrict__ C2,
        int M, int N, int K, int mode0, int mode1, int mode2)
{
    extern __shared__ char smc[];
    const uint32_t sbase = smem_u32(smc);
    const int tid  = threadIdx.x;
    const int wid  = tid >> 5;
    const int lane = tid & 31;
    const int warpM = wid & 3;
    const int warpN = wid >> 2;

    const __half* W; const float* bias; void* C; int mode;
    if (blockIdx.z == 0)      { W = W0; bias = b0_; C = C0; mode = mode0; }
    else if (blockIdx.z == 1) { W = W1; bias = b1_; C = C1; mode = mode1; }
    else                      { W = W2; bias = b2_; C = C2; mode = mode2; }

    const int rowM = blockIdx.y * 256;
    const int colN = blockIdx.x * 128;
    const __half* Ag = A + (size_t)rowM * K;
    const __half* Wg = W + (size_t)colN * K;

    const int ar = tid >> 1;            // 0..255
    const int au = (tid & 1) * 4;       // 0 or 4
    const int br = tid >> 2;            // 0..127
    const int bu = (tid & 3) * 2;       // 0,2,4,6
    const __half* agr = Ag + (size_t)ar * K;
    const __half* wgr = Wg + (size_t)br * K;

    const int a_row = lane & 15;
    const int a_u   = lane >> 4;
    const int b_row = ((lane >> 4) & 1) * 8 + (lane & 7);
    const int b_u   = (lane >> 3) & 1;

    float acc[4][4][4];
    #pragma unroll
    for (int mt = 0; mt < 4; mt++)
        #pragma unroll
        for (int nt = 0; nt < 4; nt++)
            #pragma unroll
            for (int q = 0; q < 4; q++) acc[mt][nt][q] = 0.0f;

    const int NC = K / 64;               // 16 chunks

    #pragma unroll
    for (int s = 0; s < 3; s++) {
        const uint32_t sa = sbase + s * STAGE_BYTES + ar * 128;
        const uint32_t sb = sbase + s * STAGE_BYTES + 32768 + br * 128;
        const __half* ac = agr + s * 64;
        const __half* wc = wgr + s * 64;
        #pragma unroll
        for (int i = 0; i < 4; i++) {
            const int u = au + i;
            CPA16(sa + (uint32_t)((u ^ (ar & 7)) << 4), ac + u * 8);
        }
        #pragma unroll
        for (int i = 0; i < 2; i++) {
            const int u = bu + i;
            CPA16(sb + (uint32_t)((u ^ (br & 7)) << 4), wc + u * 8);
        }
        CPA_COMMIT();
    }

    for (int c = 0; c < NC; c++) {
        const int buf = c & 3;
        CPA_WAIT2();
        __syncthreads();

        if (c + 3 < NC) {
            const int s = (c + 3) & 3;
            const uint32_t sa = sbase + s * STAGE_BYTES + ar * 128;
            const uint32_t sb = sbase + s * STAGE_BYTES + 32768 + br * 128;
            const __half* ac = agr + (c + 3) * 64;
            const __half* wc = wgr + (c + 3) * 64;
            #pragma unroll
            for (int i = 0; i < 4; i++) {
                const int u = au + i;
                CPA16(sa + (uint32_t)((u ^ (ar & 7)) << 4), ac + u * 8);
            }
            #pragma unroll
            for (int i = 0; i < 2; i++) {
                const int u = bu + i;
                CPA16(sb + (uint32_t)((u ^ (br & 7)) << 4), wc + u * 8);
            }
        }
        CPA_COMMIT();

        const uint32_t stA = sbase + buf * STAGE_BYTES;
        const uint32_t stB = stA + 32768;
        #pragma unroll
        for (int kc = 0; kc < 4; kc++) {
            uint32_t af[4][4];
            #pragma unroll
            for (int mt = 0; mt < 4; mt++) {
                const int row = warpM * 64 + mt * 16 + a_row;
                const uint32_t addr = stA + (uint32_t)(row * 128) +
                    (uint32_t)((((kc * 2 + a_u) ^ (row & 7))) << 4);
                ldmatrix_x4(af[mt][0], af[mt][1], af[mt][2], af[mt][3], addr);
            }
            uint32_t bf[4][2];
            #pragma unroll
            for (int nb = 0; nb < 2; nb++) {
                const int row = warpN * 32 + nb * 16 + b_row;
                const uint32_t addr = stB + (uint32_t)(row * 128) +
                    (uint32_t)((((kc * 2 + b_u) ^ (row & 7))) << 4);
                uint32_t r0, r1, r2, r3;
                ldmatrix_x4(r0, r1, r2, r3, addr);
                bf[nb * 2 + 0][0] = r0; bf[nb * 2 + 0][1] = r1;
                bf[nb * 2 + 1][0] = r2; bf[nb * 2 + 1][1] = r3;
            }
            #pragma unroll
            for (int mt = 0; mt < 4; mt++)
                #pragma unroll
                for (int nt = 0; nt < 4; nt++)
                    mma_f16(acc[mt][nt][0], acc[mt][nt][1],
                            acc[mt][nt][2], acc[mt][nt][3],
                            af[mt][0], af[mt][1], af[mt][2], af[mt][3],
                            bf[nt][0], bf[nt][1]);
        }
    }

    const int g = lane >> 2;
    const int t = lane & 3;
    float bb[4][2];
    #pragma unroll
    for (int nt = 0; nt < 4; nt++) {
        const int col = colN + warpN * 32 + nt * 8 + 2 * t;
        bb[nt][0] = __ldg(bias + col);
        bb[nt][1] = __ldg(bias + col + 1);
    }
    if (mode == 0) {
        float* Cf = (float*)C;
        #pragma unroll
        for (int mt = 0; mt < 4; mt++) {
            const int r0_ = rowM + warpM * 64 + mt * 16 + g;
            #pragma unroll
            for (int nt = 0; nt < 4; nt++) {
                const int col = colN + warpN * 32 + nt * 8 + 2 * t;
                float2 v0, v1;
                v0.x = acc[mt][nt][0] + bb[nt][0];
                v0.y = acc[mt][nt][1] + bb[nt][1];
                v1.x = acc[mt][nt][2] + bb[nt][0];
                v1.y = acc[mt][nt][3] + bb[nt][1];
                *(float2*)(Cf + (size_t)r0_ * N + col)       = v0;
                *(float2*)(Cf + (size_t)(r0_ + 8) * N + col) = v1;
            }
        }
    } else {
        __half* Ch = (__half*)C;
        const float sc = (mode == 3) ? QSCALE : 1.0f;
        #pragma unroll
        for (int mt = 0; mt < 4; mt++) {
            const int r0_ = rowM + warpM * 64 + mt * 16 + g;
            #pragma unroll
            for (int nt = 0; nt < 4; nt++) {
                const int col = colN + warpN * 32 + nt * 8 + 2 * t;
                *(__half2*)(Ch + (size_t)r0_ * N + col) =
                    __floats2half2_rn((acc[mt][nt][0] + bb[nt][0]) * sc,
                                      (acc[mt][nt][1] + bb[nt][1]) * sc);
                *(__half2*)(Ch + (size_t)(r0_ + 8) * N + col) =
                    __floats2half2_rn((acc[mt][nt][2] + bb[nt][0]) * sc,
                                      (acc[mt][nt][3] + bb[nt][1]) * sc);
            }
        }
    }
}

// ---------------------------------------------------------------------------
// fp16 flash attention, FA-2 register P, ldmatrix.trans V,
// exp2 (MUFU) interleaved with PV MMAs per k16-step.
// ---------------------------------------------------------------------------
#define BQ 128
#define BK 64
#define PITCHB 144                         // 72 halfs per row
#define KVBUF_B (2 * BK * PITCHB)          // 18432 B
#define ATTN_SMEM (2 * KVBUF_B)            // 36864 B

__global__ void __launch_bounds__(256, 2)
attn_tc(const __half* __restrict__ Q, const __half* __restrict__ Kg_,
        const __half* __restrict__ Vg_, __half* __restrict__ O)
{
    extern __shared__ char smc[];

    const int tid  = threadIdx.x;
    const int wid  = tid >> 5;
    const int lane = tid & 31;
    const int g    = lane >> 2;
    const int t    = lane & 3;
    const int bh   = blockIdx.y;
    const int b    = bh / NH_;
    const int h    = bh % NH_;
    const int q0   = blockIdx.x * BQ;

    const uint32_t uB0 = smem_u32(smc);
    const uint32_t uB1 = uB0 + KVBUF_B;

    const int a_row = lane & 15;
    const int a_u   = lane >> 4;
    const int b_row = ((lane >> 4) & 1) * 8 + (lane & 7);
    const int b_u   = (lane >> 3) & 1;
    const int v_row = ((lane >> 3) & 1) * 8 + (lane & 7);
    const int v_u   = (lane >> 4) & 1;

    const __half* Kg = Kg_ + (size_t)(b * S_) * HID_ + h * HD_;
    const __half* Vg = Vg_ + (size_t)(b * S_) * HID_ + h * HD_;

    const int lr = tid >> 2;            // 0..63 key row
    const int lu = (tid & 3) * 2;       // 16B units 0,2,4,6

    // ---- issue tile 0 K/V into buf0 ----
    {
        const uint32_t dk = uB0 + (uint32_t)(lr * PITCHB + lu * 16);
        const uint32_t dv = dk + (uint32_t)(BK * PITCHB);
        const __half* ks = Kg + (size_t)lr * HID_ + lu * 8;
        const __half* vs = Vg + (size_t)lr * HID_ + lu * 8;
        #pragma unroll
        for (int i = 0; i < 2; i++) {
            CPA16(dk + i * 16, ks + i * 8);
            CPA16(dv + i * 16, vs + i * 8);
        }
        CPA_COMMIT();
    }

    // ---- stage Q (pre-scaled fp16) into buf1 via cp.async ----
    {
        const int qr = tid >> 1;
        const int qu = (tid & 1) * 4;
        const uint32_t dq = uB1 + (uint32_t)(qr * PITCHB + qu * 16);
        const __half* qs = Q + (size_t)(b * S_ + q0 + qr) * HID_ + h * HD_ + qu * 8;
        #pragma unroll
        for (int i = 0; i < 4; i++) CPA16(dq + i * 16, qs + i * 8);
        CPA_COMMIT();
    }
    CPA_WAIT0();
    __syncthreads();

    uint32_t qf[4][4];
    #pragma unroll
    for (int kc = 0; kc < 4; kc++)
        ldmatrix_x4(qf[kc][0], qf[kc][1], qf[kc][2], qf[kc][3],
            uB1 + (uint32_t)((wid * 16 + a_row) * PITCHB + (kc * 2 + a_u) * 16));
    __syncthreads();

    float o[8][4];
    #pragma unroll
    for (int nt = 0; nt < 8; nt++)
        #pragma unroll
        for (int q = 0; q < 4; q++) o[nt][q] = 0.0f;
    float m0 = -1e30f, m1 = -1e30f, l0 = 0.0f, l1 = 0.0f;

    const int NT = S_ / BK;   // 32

    for (int kt = 0; kt < NT; kt++) {
        const uint32_t uKb = (kt & 1) ? uB1 : uB0;
        const uint32_t uVb = uKb + (uint32_t)(BK * PITCHB);

        if (kt + 1 < NT) {
            const uint32_t dst = (kt & 1) ? uB0 : uB1;
            const uint32_t dk = dst + (uint32_t)(lr * PITCHB + lu * 16);
            const uint32_t dv = dk + (uint32_t)(BK * PITCHB);
            const __half* ks = Kg + (size_t)((kt + 1) * BK + lr) * HID_ + lu * 8;
            const __half* vs = Vg + (size_t)((kt + 1) * BK + lr) * HID_ + lu * 8;
            #pragma unroll
            for (int i = 0; i < 2; i++) {
                CPA16(dk + i * 16, ks + i * 8);
                CPA16(dv + i * 16, vs + i * 8);
            }
            CPA_COMMIT();
            CPA_WAIT1();
        } else {
            CPA_WAIT0();
        }
        __syncthreads();

        // ---- S = Q @ K^T (4 k16 steps) ----
        float s[8][4];
        #pragma unroll
        for (int nt = 0; nt < 8; nt++)
            #pragma unroll
            for (int q = 0; q < 4; q++) s[nt][q] = 0.0f;

        #pragma unroll
        for (int kc = 0; kc < 4; kc++) {
            uint32_t bf[8][2];
            #pragma unroll
            for (int nb = 0; nb < 4; nb++) {
                uint32_t r0, r1, r2, r3;
                ldmatrix_x4(r0, r1, r2, r3,
                    uKb + (uint32_t)((nb * 16 + b_row) * PITCHB + (kc * 2 + b_u) * 16));
                bf[nb * 2 + 0][0] = r0; bf[nb * 2 + 0][1] = r1;
                bf[nb * 2 + 1][0] = r2; bf[nb * 2 + 1][1] = r3;
            }
            #pragma unroll
            for (int nt = 0; nt < 8; nt++)
                mma_f16(s[nt][0], s[nt][1], s[nt][2], s[nt][3],
                        qf[kc][0], qf[kc][1], qf[kc][2], qf[kc][3],
                        bf[nt][0], bf[nt][1]);
        }

        // ---- running max + rescale (independent of exp/PV) ----
        float mx0 = -1e30f, mx1 = -1e30f;
        #pragma unroll
        for (int nt = 0; nt < 8; nt++) {
            mx0 = fmaxf(mx0, fmaxf(s[nt][0], s[nt][1]));
            mx1 = fmaxf(mx1, fmaxf(s[nt][2], s[nt][3]));
        }
        mx0 = quad_max(mx0); mx1 = quad_max(mx1);
        const float mn0 = fmaxf(m0, mx0);
        const float mn1 = fmaxf(m1, mx1);
        const float c0r = ex2(m0 - mn0);
        const float c1r = ex2(m1 - mn1);
        m0 = mn0; m1 = mn1;
        l0 *= c0r; l1 *= c1r;
        #pragma unroll
        for (int nt = 0; nt < 8; nt++) {
            o[nt][0] *= c0r; o[nt][1] *= c0r;
            o[nt][2] *= c1r; o[nt][3] *= c1r;
        }

        // ---- interleaved exp2 + PV: per k16-step, LDSM V, exp 8 vals, 8 MMA
        float sum0 = 0.0f, sum1 = 0.0f;
        #pragma unroll
        for (int kc = 0; kc < 4; kc++) {
            uint32_t vf[8][2];
            #pragma unroll
            for (int nb = 0; nb < 4; nb++) {
                uint32_t r0, r1, r2, r3;
                ldmatrix_x4_trans(r0, r1, r2, r3,
                    uVb + (uint32_t)((kc * 16 + v_row) * PITCHB + (nb * 2 + v_u) * 16));
                vf[nb * 2 + 0][0] = r0; vf[nb * 2 + 0][1] = r1;
                vf[nb * 2 + 1][0] = r2; vf[nb * 2 + 1][1] = r3;
            }
            const int n0 = 2 * kc, n1 = 2 * kc + 1;
            float p0 = ex2(s[n0][0] - mn0);
            float p1 = ex2(s[n0][1] - mn0);
            float p2 = ex2(s[n0][2] - mn1);
            float p3 = ex2(s[n0][3] - mn1);
            float p4 = ex2(s[n1][0] - mn0);
            float p5 = ex2(s[n1][1] - mn0);
            float p6 = ex2(s[n1][2] - mn1);
            float p7 = ex2(s[n1][3] - mn1);
            sum0 += p0 + p1 + p4 + p5;
            sum1 += p2 + p3 + p6 + p7;
            __half2 h01 = __floats2half2_rn(p0, p1);
            __half2 h23 = __floats2half2_rn(p2, p3);
            __half2 h45 = __floats2half2_rn(p4, p5);
            __half2 h67 = __floats2half2_rn(p6, p7);
            const uint32_t pa0 = *(uint32_t*)&h01;
            const uint32_t pa1 = *(uint32_t*)&h23;
            const uint32_t pa2 = *(uint32_t*)&h45;
            const uint32_t pa3 = *(uint32_t*)&h67;
            #pragma unroll
            for (int nt = 0; nt < 8; nt++)
                mma_f16(o[nt][0], o[nt][1], o[nt][2], o[nt][3],
                        pa0, pa1, pa2, pa3, vf[nt][0], vf[nt][1]);
        }
        sum0 = quad_sum(sum0); sum1 = quad_sum(sum1);
        l0 += sum0;
        l1 += sum1;
        __syncthreads();
    }

    const float inv0 = 1.0f / l0;
    const float inv1 = 1.0f / l1;
    __half* Or = O + (size_t)(b * S_ + q0 + wid * 16 + g) * HID_ + h * HD_;
    #pragma unroll
    for (int nt = 0; nt < 8; nt++) {
        *(__half2*)(Or + nt * 8 + 2 * t) =
            __floats2half2_rn(o[nt][0] * inv0, o[nt][1] * inv0);
        *(__half2*)(Or + 8 * HID_ + nt * 8 + 2 * t) =
            __floats2half2_rn(o[nt][2] * inv1, o[nt][3] * inv1);
    }
}

// ---------------------------------------------------------------------------
// Launch
// ---------------------------------------------------------------------------
extern "C" void kernel_launch(void* const* d_in, const int* in_sizes, int n_in,
                              void* d_out, int out_size)
{
    const float* x  = (const float*)d_in[0];
    const float* Wq = (const float*)d_in[1];
    const float* bq = (const float*)d_in[2];
    const float* Wk = (const float*)d_in[3];
    const float* bk = (const float*)d_in[4];
    const float* Wv = (const float*)d_in[5];
    const float* bv = (const float*)d_in[6];
    const float* Wo = (const float*)d_in[7];
    const float* bo = (const float*)d_in[8];
    float* out = (float*)d_out;

    __half *qp, *kp, *vp, *ap, *xt, *wt, *wo;
    cudaGetSymbolAddress((void**)&qp, g_q);
    cudaGetSymbolAddress((void**)&kp, g_k);
    cudaGetSymbolAddress((void**)&vp, g_v);
    cudaGetSymbolAddress((void**)&ap, g_attn);
    cudaGetSymbolAddress((void**)&xt, g_xt);
    cudaGetSymbolAddress((void**)&wt, g_wt);
    cudaGetSymbolAddress((void**)&wo, g_wo);

    cudaFuncSetAttribute(gemm_tc, cudaFuncAttributeMaxDynamicSharedMemorySize,
                         GEMM_SMEM);
    cudaFuncSetAttribute(attn_tc, cudaFuncAttributeMaxDynamicSharedMemorySize,
                         ATTN_SMEM);

    // 0) convert inputs/weights to fp16
    {
        const int NX4 = MTOT * HID_ / 4;
        const int NW4 = HID_ * HID_ / 4;
        to_half<<<NX4 / 256, 256>>>(x, xt, NX4);
        dim3 wg(NW4 / 256, 1, 4);
        to_half_w4<<<wg, 256>>>(Wq, Wk, Wv, Wo,
                                wt, wt + HID_ * HID_, wt + 2 * HID_ * HID_, wo,
                                NW4);
    }

    // 1) fused QKV projections: q scaled (mode 3), k fp16 (1), v fp16 (1)
    {
        dim3 grid(HID_ / 128, MTOT / 256, 3);
        gemm_tc<<<grid, 512, GEMM_SMEM>>>(xt, wt, wt + HID_ * HID_,
                                          wt + 2 * HID_ * HID_,
                                          bq, bk, bv,
                                          (void*)qp, (void*)kp, (void*)vp,
                                          MTOT, HID_, HID_, 3, 1, 1);
    }

    // 2) attention (fp16 m16n8k16, register-P, interleaved exp2/PV)
    {
        dim3 grid(S_ / BQ, B_ * NH_);
        attn_tc<<<grid, 256, ATTN_SMEM>>>(qp, kp, vp, ap);
    }

    // 3) output projection (fp32 out)
    {
        dim3 grid(HID_ / 128, MTOT / 256, 1);
        gemm_tc<<<grid, 512, GEMM_SMEM>>>(ap, wo, wo, wo, bo, bo, bo,
                                          (void*)out, (void*)out, (void*)out,
                                          MTOT, HID_, HID_, 0, 0, 0);
    }
}